// round 1
// baseline (speedup 1.0000x reference)
#include <cuda_runtime.h>
#include <math.h>

// Problem constants
static const int Sq   = 2048;   // sequence length
static const int HIDv = 2048;   // hidden
static const int NHv  = 16;     // query heads
static const int NKVv = 4;      // kv heads
static const int Dv   = 128;    // head dim
static const int GRP  = 4;      // NH / NKV
static const int HBv  = 204;    // heavy budget
static const int RBv  = 204;    // recent budget
#define SCALE 0.08838834764831845f  // 1/sqrt(128)

// Scratch (device globals; allocation-free)
__device__ float g_q[2048 * 2048];
__device__ float g_k[2048 * 512];
__device__ float g_v[2048 * 512];
__device__ float g_scores[16LL * 2048 * 2048];       // 268 MB
__device__ float g_rowmax[16 * 2048];
__device__ float g_rowsum[16 * 2048];
__device__ float g_colpart[16 * 128 * 2048];         // per-chunk partial colsums
__device__ float g_colsum[16 * 2048];
__device__ int   g_heavy_idx[16 * 204];
__device__ float g_attnout[2048 * 2048];

// ---------------------------------------------------------------------------
// Generic SGEMM: C[M,N] = A[M,K] @ B[K,N], row-major, M%64==0, N%64==0, K%16==0
// 64x64 tile, BK=16, 256 threads, 4x4 per thread.
// ---------------------------------------------------------------------------
__global__ __launch_bounds__(256) void sgemm_kernel(
    const float* __restrict__ A, const float* __restrict__ B,
    float* __restrict__ C, int M, int N, int K)
{
    __shared__ float As[16][64];
    __shared__ float Bs[16][64];
    int tid = threadIdx.x;
    int tx = tid & 15, ty = tid >> 4;
    int row0 = blockIdx.y * 64, col0 = blockIdx.x * 64;

    float acc[4][4];
#pragma unroll
    for (int i = 0; i < 4; i++)
#pragma unroll
        for (int j = 0; j < 4; j++) acc[i][j] = 0.f;

    for (int k0 = 0; k0 < K; k0 += 16) {
        {   // A tile 64x16
            int l = tid * 4;
            int r = l >> 4, c = l & 15;
            float4 v = *reinterpret_cast<const float4*>(&A[(size_t)(row0 + r) * K + k0 + c]);
            As[c + 0][r] = v.x; As[c + 1][r] = v.y; As[c + 2][r] = v.z; As[c + 3][r] = v.w;
        }
        {   // B tile 16x64
            int l = tid * 4;
            int r = l >> 6, c = l & 63;
            float4 v = *reinterpret_cast<const float4*>(&B[(size_t)(k0 + r) * N + col0 + c]);
            *reinterpret_cast<float4*>(&Bs[r][c]) = v;
        }
        __syncthreads();
#pragma unroll
        for (int kk = 0; kk < 16; kk++) {
            float a[4], b[4];
#pragma unroll
            for (int i = 0; i < 4; i++) a[i] = As[kk][ty * 4 + i];
#pragma unroll
            for (int j = 0; j < 4; j++) b[j] = Bs[kk][tx * 4 + j];
#pragma unroll
            for (int i = 0; i < 4; i++)
#pragma unroll
                for (int j = 0; j < 4; j++) acc[i][j] += a[i] * b[j];
        }
        __syncthreads();
    }
#pragma unroll
    for (int i = 0; i < 4; i++) {
        int r = row0 + ty * 4 + i;
#pragma unroll
        for (int j = 0; j < 4; j++)
            C[(size_t)r * N + col0 + tx * 4 + j] = acc[i][j];
    }
}

// ---------------------------------------------------------------------------
// RoPE in place. x layout [S, H, 128]. Matches JAX: freq = fp32(s * inv_freq),
// trig evaluated accurately (double) on that fp32 value.
// ---------------------------------------------------------------------------
__global__ void rope_kernel(float* x, int H)
{
    int idx = blockIdx.x * blockDim.x + threadIdx.x;
    int total = Sq * H * 64;
    if (idx >= total) return;
    int j = idx & 63;
    int t = idx >> 6;
    int h = t % H;
    int s = t / H;
    float inv = powf(10000.0f, -(float)(2 * j) / 128.0f);
    float f = (float)s * inv;
    double fd = (double)f;
    float c = (float)cos(fd);
    float sn = (float)sin(fd);
    size_t base = ((size_t)s * H + h) * 128;
    float x1 = x[base + j], x2 = x[base + 64 + j];
    x[base + j]      = x1 * c - x2 * sn;
    x[base + 64 + j] = x2 * c + x1 * sn;
}

// ---------------------------------------------------------------------------
// Scores: scores[h][i][j] = dot(q[i,h,:], k[j,h/4,:]) * SCALE  (j <= i)
// 64x64 tile per block, only lower-triangular tiles run.
// ---------------------------------------------------------------------------
__global__ __launch_bounds__(256) void scores_kernel(
    const float* __restrict__ q, const float* __restrict__ kmat)
{
    int jt = blockIdx.x, it = blockIdx.y, h = blockIdx.z;
    if (jt > it) return;
    int kv = h / GRP;
    __shared__ float Qs[16][64];
    __shared__ float Ks[16][64];
    int tid = threadIdx.x;
    int tx = tid & 15, ty = tid >> 4;
    int i0 = it * 64, j0 = jt * 64;

    float acc[4][4];
#pragma unroll
    for (int i = 0; i < 4; i++)
#pragma unroll
        for (int j = 0; j < 4; j++) acc[i][j] = 0.f;

    for (int d0 = 0; d0 < Dv; d0 += 16) {
        {
            int l = tid * 4; int r = l >> 4, c = l & 15;
            float4 v = *reinterpret_cast<const float4*>(
                &q[(size_t)(i0 + r) * HIDv + h * Dv + d0 + c]);
            Qs[c + 0][r] = v.x; Qs[c + 1][r] = v.y; Qs[c + 2][r] = v.z; Qs[c + 3][r] = v.w;
        }
        {
            int l = tid * 4; int r = l >> 4, c = l & 15;
            float4 v = *reinterpret_cast<const float4*>(
                &kmat[(size_t)(j0 + r) * (NKVv * Dv) + kv * Dv + d0 + c]);
            Ks[c + 0][r] = v.x; Ks[c + 1][r] = v.y; Ks[c + 2][r] = v.z; Ks[c + 3][r] = v.w;
        }
        __syncthreads();
#pragma unroll
        for (int kk = 0; kk < 16; kk++) {
            float a[4], b[4];
#pragma unroll
            for (int i = 0; i < 4; i++) a[i] = Qs[kk][ty * 4 + i];
#pragma unroll
            for (int j = 0; j < 4; j++) b[j] = Ks[kk][tx * 4 + j];
#pragma unroll
            for (int i = 0; i < 4; i++)
#pragma unroll
                for (int j = 0; j < 4; j++) acc[i][j] += a[i] * b[j];
        }
        __syncthreads();
    }
#pragma unroll
    for (int i = 0; i < 4; i++) {
        int gi = i0 + ty * 4 + i;
#pragma unroll
        for (int j = 0; j < 4; j++) {
            int gj = j0 + tx * 4 + j;
            float val = (gj <= gi) ? acc[i][j] * SCALE : -3.0e38f;
            g_scores[((size_t)h * Sq + gi) * Sq + gj] = val;
        }
    }
}

// ---------------------------------------------------------------------------
// Per-row max and sum(exp) over causal entries j <= i.
// ---------------------------------------------------------------------------
__global__ __launch_bounds__(256) void rowstat_kernel()
{
    int i = blockIdx.x, h = blockIdx.y;
    const float* row = &g_scores[((size_t)h * Sq + i) * Sq];
    int n = i + 1;
    __shared__ float red[256];
    int tid = threadIdx.x;

    float m = -3.4e38f;
    for (int j = tid; j < n; j += 256) m = fmaxf(m, row[j]);
    red[tid] = m; __syncthreads();
    for (int w = 128; w > 0; w >>= 1) {
        if (tid < w) red[tid] = fmaxf(red[tid], red[tid + w]);
        __syncthreads();
    }
    m = red[0]; __syncthreads();

    float sum = 0.f;
    for (int j = tid; j < n; j += 256) sum += expf(row[j] - m);
    red[tid] = sum; __syncthreads();
    for (int w = 128; w > 0; w >>= 1) {
        if (tid < w) red[tid] += red[tid + w];
        __syncthreads();
    }
    if (tid == 0) { g_rowmax[h * Sq + i] = m; g_rowsum[h * Sq + i] = red[0]; }
}

// ---------------------------------------------------------------------------
// Column-sum of softmax probs: partial sums per 16-row chunk (deterministic).
// ---------------------------------------------------------------------------
__global__ __launch_bounds__(256) void colsum_kernel()
{
    int chunk = blockIdx.x, h = blockIdx.y;
    int i0 = chunk * 16;
    __shared__ float cs[2048];
    int tid = threadIdx.x;
    for (int j = tid; j < Sq; j += 256) cs[j] = 0.f;
    __syncthreads();
    for (int r = 0; r < 16; r++) {
        int i = i0 + r;
        float m = g_rowmax[h * Sq + i];
        float invl = 1.0f / g_rowsum[h * Sq + i];
        const float* row = &g_scores[((size_t)h * Sq + i) * Sq];
        for (int j = tid; j <= i; j += 256) cs[j] += expf(row[j] - m) * invl;
    }
    __syncthreads();
    float* dst = &g_colpart[((size_t)h * 128 + chunk) * Sq];
    for (int j = tid; j < Sq; j += 256) dst[j] = cs[j];
}

__global__ void colreduce_kernel()
{
    int j = blockIdx.x * 256 + threadIdx.x;
    int h = blockIdx.y;
    float s = 0.f;
    for (int c = 0; c < 128; c++) s += g_colpart[((size_t)h * 128 + c) * Sq + j];
    g_colsum[h * Sq + j] = s;
}

// ---------------------------------------------------------------------------
// Top-204 per head via bitonic sort (descending) + deterministic index build.
// ---------------------------------------------------------------------------
__global__ __launch_bounds__(1024) void topk_kernel()
{
    int h = blockIdx.x;
    __shared__ float sorted[2048];
    int tid = threadIdx.x;
    for (int j = tid; j < Sq; j += 1024) sorted[j] = g_colsum[h * Sq + j];
    __syncthreads();

    for (int kk = 2; kk <= 2048; kk <<= 1) {
        for (int jj = kk >> 1; jj > 0; jj >>= 1) {
            for (int t = tid; t < 2048; t += 1024) {
                int ixj = t ^ jj;
                if (ixj > t) {
                    float a = sorted[t], b = sorted[ixj];
                    bool desc = ((t & kk) == 0);
                    bool sw = desc ? (a < b) : (a > b);
                    if (sw) { sorted[t] = b; sorted[ixj] = a; }
                }
            }
            __syncthreads();
        }
    }
    float thresh = sorted[HBv - 1];
    if (tid == 0) {
        int cnt = 0;
        for (int j = 0; j < Sq && cnt < HBv; j++)
            if (g_colsum[h * Sq + j] > thresh) g_heavy_idx[h * HBv + cnt++] = j;
        for (int j = 0; j < Sq && cnt < HBv; j++)
            if (g_colsum[h * Sq + j] == thresh) g_heavy_idx[h * HBv + cnt++] = j;
    }
}

// ---------------------------------------------------------------------------
// Final sparse attention: per (h, i), kept = band [i-204, i] U heavy(<band).
// Masked softmax over kept, then p @ V.
// ---------------------------------------------------------------------------
__global__ __launch_bounds__(256) void attnout_kernel(const float* __restrict__ v)
{
    int i = blockIdx.x, h = blockIdx.y;
    int kv = h / GRP;
    int tid = threadIdx.x;
    __shared__ int jlist[512];
    __shared__ float pv[512];
    __shared__ float red[256];
    __shared__ int n_s;

    int lo = i - RBv; if (lo < 0) lo = 0;
    int nb = i - lo + 1;
    for (int t = tid; t < nb; t += 256) jlist[t] = lo + t;
    if (tid == 0) {
        int cnt = nb;
        for (int t = 0; t < HBv; t++) {
            int j = g_heavy_idx[h * HBv + t];
            if (j < lo) jlist[cnt++] = j;
        }
        n_s = cnt;
    }
    __syncthreads();
    int n = n_s;
    const float* row = &g_scores[((size_t)h * Sq + i) * Sq];

    float m = -3.4e38f;
    for (int t = tid; t < n; t += 256) m = fmaxf(m, row[jlist[t]]);
    red[tid] = m; __syncthreads();
    for (int w = 128; w > 0; w >>= 1) {
        if (tid < w) red[tid] = fmaxf(red[tid], red[tid + w]);
        __syncthreads();
    }
    m = red[0]; __syncthreads();

    float sum = 0.f;
    for (int t = tid; t < n; t += 256) {
        float p = expf(row[jlist[t]] - m);
        pv[t] = p;
        sum += p;
    }
    red[tid] = sum; __syncthreads();
    for (int w = 128; w > 0; w >>= 1) {
        if (tid < w) red[tid] += red[tid + w];
        __syncthreads();
    }
    float invl = 1.0f / red[0];
    __syncthreads();

    // p @ V : two threads per output dim
    int d = tid & 127;
    int half = tid >> 7;
    float acc = 0.f;
    for (int t = half; t < n; t += 2)
        acc += pv[t] * v[(size_t)jlist[t] * (NKVv * Dv) + kv * Dv + d];
    red[tid] = acc; __syncthreads();
    if (tid < 128)
        g_attnout[(size_t)i * HIDv + h * Dv + tid] = (red[tid] + red[tid + 128]) * invl;
}

// ---------------------------------------------------------------------------
extern "C" void kernel_launch(void* const* d_in, const int* in_sizes, int n_in,
                              void* d_out, int out_size)
{
    const float* hs = (const float*)d_in[0];
    const float* Wq = (const float*)d_in[1];
    const float* Wk = (const float*)d_in[2];
    const float* Wv = (const float*)d_in[3];
    const float* Wo = (const float*)d_in[4];
    float* out = (float*)d_out;

    void* p;
    cudaGetSymbolAddress(&p, g_q);       float* qp  = (float*)p;
    cudaGetSymbolAddress(&p, g_k);       float* kp  = (float*)p;
    cudaGetSymbolAddress(&p, g_v);       float* vp  = (float*)p;
    cudaGetSymbolAddress(&p, g_attnout); float* aop = (float*)p;

    // Projections
    sgemm_kernel<<<dim3(HIDv / 64, Sq / 64), 256>>>(hs, Wq, qp, Sq, HIDv, HIDv);
    sgemm_kernel<<<dim3((NKVv * Dv) / 64, Sq / 64), 256>>>(hs, Wk, kp, Sq, NKVv * Dv, HIDv);
    sgemm_kernel<<<dim3((NKVv * Dv) / 64, Sq / 64), 256>>>(hs, Wv, vp, Sq, NKVv * Dv, HIDv);

    // RoPE
    rope_kernel<<<(Sq * NHv * 64 + 255) / 256, 256>>>(qp, NHv);
    rope_kernel<<<(Sq * NKVv * 64 + 255) / 256, 256>>>(kp, NKVv);

    // Causal scores (stored)
    scores_kernel<<<dim3(Sq / 64, Sq / 64, NHv), 256>>>(qp, kp);

    // H2O oracle
    rowstat_kernel<<<dim3(Sq, NHv), 256>>>();
    colsum_kernel<<<dim3(Sq / 16, NHv), 256>>>();
    colreduce_kernel<<<dim3(Sq / 256, NHv), 256>>>();
    topk_kernel<<<NHv, 1024>>>();

    // Sparse attention output
    attnout_kernel<<<dim3(Sq, NHv), 256>>>(vp);

    // Output projection
    sgemm_kernel<<<dim3(HIDv / 64, Sq / 64), 256>>>(aop, Wo, out, Sq, HIDv, HIDv);
}

// round 3
// speedup vs baseline: 1.5316x; 1.5316x over previous
#include <cuda_runtime.h>
#include <math.h>
#include <stdint.h>

// Problem constants
static const int Sq   = 2048;
static const int HIDv = 2048;
static const int NHv  = 16;
static const int NKVv = 4;
static const int Dv   = 128;
static const int GRP  = 4;
static const int HBv  = 204;
static const int RBv  = 204;
#define SCALE 0.08838834764831845f  // 1/sqrt(128)

// Scratch (device globals; allocation-free)
__device__ float g_q[2048 * 2048];
__device__ float g_k[2048 * 512];
__device__ float g_v[2048 * 512];
__device__ float g_wt[2048 * 2048];                  // transposed weights scratch
__device__ float g_scores[16LL * 2048 * 2048];       // 268 MB
__device__ float g_rowmax[16 * 2048];
__device__ float g_rowsum[16 * 2048];
__device__ float g_colpart[16 * 128 * 2048];
__device__ float g_colsum[16 * 2048];
__device__ int   g_heavy_idx[16 * 204];
__device__ float g_attnout[2048 * 2048];

// ===========================================================================
// tf32 mma.sync helpers (baseline sm_100 PTX — no 'a' features)
// ===========================================================================
__device__ __forceinline__ uint32_t f2tf(float x) {
    uint32_t r;
    asm("cvt.rna.tf32.f32 %0, %1;" : "=r"(r) : "f"(x));
    return r;
}

__device__ __forceinline__ void mma16n8k8(float* c, const uint32_t* a, const uint32_t* b) {
    asm volatile(
        "mma.sync.aligned.m16n8k8.row.col.f32.tf32.tf32.f32 "
        "{%0,%1,%2,%3}, {%4,%5,%6,%7}, {%8,%9}, {%0,%1,%2,%3};"
        : "+f"(c[0]), "+f"(c[1]), "+f"(c[2]), "+f"(c[3])
        : "r"(a[0]), "r"(a[1]), "r"(a[2]), "r"(a[3]), "r"(b[0]), "r"(b[1]));
}

// Shared tile layout: 128 rows x 32 tf32, padded stride 40 (16B-aligned float4)
#define TSTRIDE 40

// Load one 128x32 K-chunk (converted to tf32 bits) from a K-major matrix.
__device__ __forceinline__ void load_tile(
    uint32_t* dst, const float* __restrict__ src, int ld, int r0, int k0, int tid)
{
#pragma unroll
    for (int it = 0; it < 4; it++) {
        int s = tid + it * 256;
        int r = s >> 3, c4 = (s & 7) * 4;
        float4 v = *reinterpret_cast<const float4*>(&src[(size_t)(r0 + r) * ld + k0 + c4]);
        uint4 u = make_uint4(f2tf(v.x), f2tf(v.y), f2tf(v.z), f2tf(v.w));
        *reinterpret_cast<uint4*>(&dst[r * TSTRIDE + c4]) = u;
    }
}

// Inner product over one 32-wide K chunk: acc[2][8][4] += A-frag x B-frag
__device__ __forceinline__ void tile_mma(
    float (*acc)[8][4], const uint32_t* As, const uint32_t* Bs,
    int wm, int wn, int lane)
{
#pragma unroll
    for (int kk = 0; kk < 4; kk++) {
        uint32_t a[2][4], b[8][2];
        int kA = kk * 8 + (lane & 3);
#pragma unroll
        for (int mt = 0; mt < 2; mt++) {
            int mr = wm * 32 + mt * 16 + (lane >> 2);
            a[mt][0] = As[mr * TSTRIDE + kA];
            a[mt][1] = As[(mr + 8) * TSTRIDE + kA];
            a[mt][2] = As[mr * TSTRIDE + kA + 4];
            a[mt][3] = As[(mr + 8) * TSTRIDE + kA + 4];
        }
#pragma unroll
        for (int nt = 0; nt < 8; nt++) {
            int nc = wn * 64 + nt * 8 + (lane >> 2);
            b[nt][0] = Bs[nc * TSTRIDE + kA];
            b[nt][1] = Bs[nc * TSTRIDE + kA + 4];
        }
#pragma unroll
        for (int nt = 0; nt < 8; nt++)
#pragma unroll
            for (int mt = 0; mt < 2; mt++)
                mma16n8k8(acc[mt][nt], a[mt], b[nt]);
    }
}

// ---------------------------------------------------------------------------
// Generic GEMM: C[M,N] = A[M,K] @ Bt[N,K]^T, tf32 tensor cores.
// Grid: (N/128, M/128), 256 threads.
// ---------------------------------------------------------------------------
__global__ __launch_bounds__(256) void gemm_mma_kernel(
    const float* __restrict__ A, int lda,
    const float* __restrict__ Bt, int ldb,
    float* __restrict__ C, int ldc, int K)
{
    __shared__ uint32_t As[128 * TSTRIDE];
    __shared__ uint32_t Bs[128 * TSTRIDE];
    int tid = threadIdx.x;
    int wid = tid >> 5, lane = tid & 31;
    int wm = wid & 3, wn = wid >> 2;
    int row0 = blockIdx.y * 128, col0 = blockIdx.x * 128;

    float acc[2][8][4];
#pragma unroll
    for (int mt = 0; mt < 2; mt++)
#pragma unroll
        for (int nt = 0; nt < 8; nt++)
#pragma unroll
            for (int e = 0; e < 4; e++) acc[mt][nt][e] = 0.f;

    for (int k0 = 0; k0 < K; k0 += 32) {
        load_tile(As, A, lda, row0, k0, tid);
        load_tile(Bs, Bt, ldb, col0, k0, tid);
        __syncthreads();
        tile_mma(acc, As, Bs, wm, wn, lane);
        __syncthreads();
    }

#pragma unroll
    for (int mt = 0; mt < 2; mt++) {
        int r0 = row0 + wm * 32 + mt * 16 + (lane >> 2);
#pragma unroll
        for (int nt = 0; nt < 8; nt++) {
            int c = col0 + wn * 64 + nt * 8 + (lane & 3) * 2;
            *reinterpret_cast<float2*>(&C[(size_t)r0 * ldc + c]) =
                make_float2(acc[mt][nt][0], acc[mt][nt][1]);
            *reinterpret_cast<float2*>(&C[(size_t)(r0 + 8) * ldc + c]) =
                make_float2(acc[mt][nt][2], acc[mt][nt][3]);
        }
    }
}

// ---------------------------------------------------------------------------
// Causal scores: g_scores[h][i][j] = (q_i . k_j)*SCALE for j<=i else -3e38.
// Grid: (Sq/128, Sq/128, NH); skips upper-triangular tiles.
// ---------------------------------------------------------------------------
__global__ __launch_bounds__(256) void scores_mma_kernel(
    const float* __restrict__ q, const float* __restrict__ k)
{
    int jt = blockIdx.x, it = blockIdx.y, h = blockIdx.z;
    if (jt > it) return;

    __shared__ uint32_t As[128 * TSTRIDE];
    __shared__ uint32_t Bs[128 * TSTRIDE];
    int tid = threadIdx.x;
    int wid = tid >> 5, lane = tid & 31;
    int wm = wid & 3, wn = wid >> 2;
    int row0 = it * 128, col0 = jt * 128;

    const float* Aq = q + h * Dv;
    const float* Bk = k + (h >> 2) * Dv;

    float acc[2][8][4];
#pragma unroll
    for (int mt = 0; mt < 2; mt++)
#pragma unroll
        for (int nt = 0; nt < 8; nt++)
#pragma unroll
            for (int e = 0; e < 4; e++) acc[mt][nt][e] = 0.f;

    for (int k0 = 0; k0 < Dv; k0 += 32) {
        load_tile(As, Aq, HIDv, row0, k0, tid);
        load_tile(Bs, Bk, NKVv * Dv, col0, k0, tid);
        __syncthreads();
        tile_mma(acc, As, Bs, wm, wn, lane);
        __syncthreads();
    }

#pragma unroll
    for (int mt = 0; mt < 2; mt++) {
        int r0 = row0 + wm * 32 + mt * 16 + (lane >> 2);
#pragma unroll
        for (int nt = 0; nt < 8; nt++) {
            int c = col0 + wn * 64 + nt * 8 + (lane & 3) * 2;
            float2 v0, v1;
            v0.x = (c + 0 <= r0) ? acc[mt][nt][0] * SCALE : -3.0e38f;
            v0.y = (c + 1 <= r0) ? acc[mt][nt][1] * SCALE : -3.0e38f;
            v1.x = (c + 0 <= r0 + 8) ? acc[mt][nt][2] * SCALE : -3.0e38f;
            v1.y = (c + 1 <= r0 + 8) ? acc[mt][nt][3] * SCALE : -3.0e38f;
            *reinterpret_cast<float2*>(&g_scores[((size_t)h * Sq + r0) * Sq + c]) = v0;
            *reinterpret_cast<float2*>(&g_scores[((size_t)h * Sq + r0 + 8) * Sq + c]) = v1;
        }
    }
}

// ---------------------------------------------------------------------------
// Weight transpose: W[K,N] -> Wt[N,K]
// ---------------------------------------------------------------------------
__global__ void transpose_kernel(const float* __restrict__ W, float* __restrict__ Wt,
                                 int K, int N)
{
    __shared__ float t[32][33];
    int n0 = blockIdx.x * 32, k0 = blockIdx.y * 32;
    int tx = threadIdx.x, ty = threadIdx.y;  // 32 x 8
#pragma unroll
    for (int i = 0; i < 4; i++)
        t[ty + i * 8][tx] = W[(size_t)(k0 + ty + i * 8) * N + n0 + tx];
    __syncthreads();
#pragma unroll
    for (int i = 0; i < 4; i++)
        Wt[(size_t)(n0 + ty + i * 8) * K + k0 + tx] = t[tx][ty + i * 8];
}

// ---------------------------------------------------------------------------
// RoPE in place. x layout [S, H, 128].
// ---------------------------------------------------------------------------
__global__ void rope_kernel(float* x, int H)
{
    int idx = blockIdx.x * blockDim.x + threadIdx.x;
    int total = Sq * H * 64;
    if (idx >= total) return;
    int j = idx & 63;
    int t = idx >> 6;
    int h = t % H;
    int s = t / H;
    float inv = powf(10000.0f, -(float)(2 * j) / 128.0f);
    float f = (float)s * inv;
    double fd = (double)f;
    float c = (float)cos(fd);
    float sn = (float)sin(fd);
    size_t base = ((size_t)s * H + h) * 128;
    float x1 = x[base + j], x2 = x[base + 64 + j];
    x[base + j]      = x1 * c - x2 * sn;
    x[base + 64 + j] = x2 * c + x1 * sn;
}

// ---------------------------------------------------------------------------
// Per-row max and sum(exp) over causal entries j <= i (oracle only).
// ---------------------------------------------------------------------------
__global__ __launch_bounds__(256) void rowstat_kernel()
{
    int i = blockIdx.x, h = blockIdx.y;
    const float* row = &g_scores[((size_t)h * Sq + i) * Sq];
    int n = i + 1;
    __shared__ float red[256];
    int tid = threadIdx.x;

    float m = -3.4e38f;
    for (int j = tid; j < n; j += 256) m = fmaxf(m, row[j]);
    red[tid] = m; __syncthreads();
    for (int w = 128; w > 0; w >>= 1) {
        if (tid < w) red[tid] = fmaxf(red[tid], red[tid + w]);
        __syncthreads();
    }
    m = red[0]; __syncthreads();

    float sum = 0.f;
    for (int j = tid; j < n; j += 256) sum += expf(row[j] - m);
    red[tid] = sum; __syncthreads();
    for (int w = 128; w > 0; w >>= 1) {
        if (tid < w) red[tid] += red[tid + w];
        __syncthreads();
    }
    if (tid == 0) { g_rowmax[h * Sq + i] = m; g_rowsum[h * Sq + i] = red[0]; }
}

// ---------------------------------------------------------------------------
// Column-sum of softmax probs: partial sums per 16-row chunk (deterministic).
// ---------------------------------------------------------------------------
__global__ __launch_bounds__(256) void colsum_kernel()
{
    int chunk = blockIdx.x, h = blockIdx.y;
    int i0 = chunk * 16;
    __shared__ float cs[2048];
    int tid = threadIdx.x;
    for (int j = tid; j < Sq; j += 256) cs[j] = 0.f;
    __syncthreads();
    for (int r = 0; r < 16; r++) {
        int i = i0 + r;
        float m = g_rowmax[h * Sq + i];
        float invl = 1.0f / g_rowsum[h * Sq + i];
        const float* row = &g_scores[((size_t)h * Sq + i) * Sq];
        for (int j = tid; j <= i; j += 256) cs[j] += expf(row[j] - m) * invl;
    }
    __syncthreads();
    float* dst = &g_colpart[((size_t)h * 128 + chunk) * Sq];
    for (int j = tid; j < Sq; j += 256) dst[j] = cs[j];
}

__global__ void colreduce_kernel()
{
    int j = blockIdx.x * 256 + threadIdx.x;
    int h = blockIdx.y;
    float s = 0.f;
    for (int c = 0; c < 128; c++) s += g_colpart[((size_t)h * 128 + c) * Sq + j];
    g_colsum[h * Sq + j] = s;
}

// ---------------------------------------------------------------------------
// Top-204 per head via bitonic sort (descending) + deterministic index build.
// ---------------------------------------------------------------------------
__global__ __launch_bounds__(1024) void topk_kernel()
{
    int h = blockIdx.x;
    __shared__ float sorted[2048];
    int tid = threadIdx.x;
    for (int j = tid; j < Sq; j += 1024) sorted[j] = g_colsum[h * Sq + j];
    __syncthreads();

    for (int kk = 2; kk <= 2048; kk <<= 1) {
        for (int jj = kk >> 1; jj > 0; jj >>= 1) {
            for (int t = tid; t < 2048; t += 1024) {
                int ixj = t ^ jj;
                if (ixj > t) {
                    float a = sorted[t], b = sorted[ixj];
                    bool desc = ((t & kk) == 0);
                    bool sw = desc ? (a < b) : (a > b);
                    if (sw) { sorted[t] = b; sorted[ixj] = a; }
                }
            }
            __syncthreads();
        }
    }
    float thresh = sorted[HBv - 1];
    if (tid == 0) {
        int cnt = 0;
        for (int j = 0; j < Sq && cnt < HBv; j++)
            if (g_colsum[h * Sq + j] > thresh) g_heavy_idx[h * HBv + cnt++] = j;
        for (int j = 0; j < Sq && cnt < HBv; j++)
            if (g_colsum[h * Sq + j] == thresh) g_heavy_idx[h * HBv + cnt++] = j;
    }
}

// ---------------------------------------------------------------------------
// Final sparse attention: per (h, i), kept = band [i-204, i] U heavy(<band).
// ---------------------------------------------------------------------------
__global__ __launch_bounds__(256) void attnout_kernel(const float* __restrict__ v)
{
    int i = blockIdx.x, h = blockIdx.y;
    int kv = h / GRP;
    int tid = threadIdx.x;
    __shared__ int jlist[512];
    __shared__ float pv[512];
    __shared__ float red[256];
    __shared__ int n_s;

    int lo = i - RBv; if (lo < 0) lo = 0;
    int nb = i - lo + 1;
    for (int t = tid; t < nb; t += 256) jlist[t] = lo + t;
    if (tid == 0) {
        int cnt = nb;
        for (int t = 0; t < HBv; t++) {
            int j = g_heavy_idx[h * HBv + t];
            if (j < lo) jlist[cnt++] = j;
        }
        n_s = cnt;
    }
    __syncthreads();
    int n = n_s;
    const float* row = &g_scores[((size_t)h * Sq + i) * Sq];

    float m = -3.4e38f;
    for (int t = tid; t < n; t += 256) m = fmaxf(m, row[jlist[t]]);
    red[tid] = m; __syncthreads();
    for (int w = 128; w > 0; w >>= 1) {
        if (tid < w) red[tid] = fmaxf(red[tid], red[tid + w]);
        __syncthreads();
    }
    m = red[0]; __syncthreads();

    float sum = 0.f;
    for (int t = tid; t < n; t += 256) {
        float p = expf(row[jlist[t]] - m);
        pv[t] = p;
        sum += p;
    }
    red[tid] = sum; __syncthreads();
    for (int w = 128; w > 0; w >>= 1) {
        if (tid < w) red[tid] += red[tid + w];
        __syncthreads();
    }
    float invl = 1.0f / red[0];
    __syncthreads();

    int d = tid & 127;
    int half = tid >> 7;
    float acc = 0.f;
    for (int t = half; t < n; t += 2)
        acc += pv[t] * v[(size_t)jlist[t] * (NKVv * Dv) + kv * Dv + d];
    red[tid] = acc; __syncthreads();
    if (tid < 128)
        g_attnout[(size_t)i * HIDv + h * Dv + tid] = (red[tid] + red[tid + 128]) * invl;
}

// ---------------------------------------------------------------------------
extern "C" void kernel_launch(void* const* d_in, const int* in_sizes, int n_in,
                              void* d_out, int out_size)
{
    const float* hs = (const float*)d_in[0];
    const float* Wq = (const float*)d_in[1];
    const float* Wk = (const float*)d_in[2];
    const float* Wv = (const float*)d_in[3];
    const float* Wo = (const float*)d_in[4];
    float* out = (float*)d_out;

    void* p;
    cudaGetSymbolAddress(&p, g_q);       float* qp  = (float*)p;
    cudaGetSymbolAddress(&p, g_k);       float* kp  = (float*)p;
    cudaGetSymbolAddress(&p, g_v);       float* vp  = (float*)p;
    cudaGetSymbolAddress(&p, g_wt);      float* wt  = (float*)p;
    cudaGetSymbolAddress(&p, g_attnout); float* aop = (float*)p;

    dim3 tb(32, 8);

    // Q projection
    transpose_kernel<<<dim3(HIDv / 32, HIDv / 32), tb>>>(Wq, wt, HIDv, HIDv);
    gemm_mma_kernel<<<dim3(HIDv / 128, Sq / 128), 256>>>(hs, HIDv, wt, HIDv, qp, HIDv, HIDv);

    // K projection
    transpose_kernel<<<dim3((NKVv * Dv) / 32, HIDv / 32), tb>>>(Wk, wt, HIDv, NKVv * Dv);
    gemm_mma_kernel<<<dim3((NKVv * Dv) / 128, Sq / 128), 256>>>(hs, HIDv, wt, HIDv, kp, NKVv * Dv, HIDv);

    // V projection
    transpose_kernel<<<dim3((NKVv * Dv) / 32, HIDv / 32), tb>>>(Wv, wt, HIDv, NKVv * Dv);
    gemm_mma_kernel<<<dim3((NKVv * Dv) / 128, Sq / 128), 256>>>(hs, HIDv, wt, HIDv, vp, NKVv * Dv, HIDv);

    // RoPE
    rope_kernel<<<(Sq * NHv * 64 + 255) / 256, 256>>>(qp, NHv);
    rope_kernel<<<(Sq * NKVv * 64 + 255) / 256, 256>>>(kp, NKVv);

    // Causal scores via tf32 tensor cores
    scores_mma_kernel<<<dim3(Sq / 128, Sq / 128, NHv), 256>>>(qp, kp);

    // H2O oracle
    rowstat_kernel<<<dim3(Sq, NHv), 256>>>();
    colsum_kernel<<<dim3(Sq / 16, NHv), 256>>>();
    colreduce_kernel<<<dim3(Sq / 256, NHv), 256>>>();
    topk_kernel<<<NHv, 1024>>>();

    // Sparse attention output (exact fp32)
    attnout_kernel<<<dim3(Sq, NHv), 256>>>(vp);

    // Output projection
    transpose_kernel<<<dim3(HIDv / 32, HIDv / 32), tb>>>(Wo, wt, HIDv, HIDv);
    gemm_mma_kernel<<<dim3(HIDv / 128, Sq / 128), 256>>>(aop, HIDv, wt, HIDv, out, HIDv, HIDv);
}

// round 4
// speedup vs baseline: 1.7666x; 1.1534x over previous
#include <cuda_runtime.h>
#include <math.h>
#include <stdint.h>

// Problem constants
static const int Sq   = 2048;
static const int HIDv = 2048;
static const int NHv  = 16;
static const int NKVv = 4;
static const int Dv   = 128;
static const int GRP  = 4;
static const int HBv  = 204;
static const int RBv  = 204;
static const int QKV  = 3072;   // fused projection width (2048 q + 512 k + 512 v)
#define SCALE 0.08838834764831845f  // 1/sqrt(128)

// Scratch (device globals; allocation-free)
__device__ float g_qkv[2048 * 3072];                 // q | k | v fused
__device__ float g_wt[3072 * 2048];                  // transposed weights scratch
__device__ float g_scores[16LL * 2048 * 2048];       // logits then probs (268 MB)
__device__ float g_rowsum[16 * 2048];
__device__ float g_colpart[16 * 128 * 2048];
__device__ float g_colsum[16 * 2048];
__device__ int   g_heavy_idx[16 * 204];
__device__ float g_attnout[2048 * 2048];

// ===========================================================================
// tf32 mma.sync helpers (baseline sm_100 PTX)
// ===========================================================================
__device__ __forceinline__ uint32_t f2tf(float x) {
    uint32_t r;
    asm("cvt.rna.tf32.f32 %0, %1;" : "=r"(r) : "f"(x));
    return r;
}
__device__ __forceinline__ uint32_t smem_u32(const void* p) {
    uint32_t a;
    asm("{ .reg .u64 t; cvta.to.shared.u64 t, %1; cvt.u32.u64 %0, t; }" : "=r"(a) : "l"(p));
    return a;
}
__device__ __forceinline__ void mma16n8k8(float* c, const uint32_t* a, const uint32_t* b) {
    asm volatile(
        "mma.sync.aligned.m16n8k8.row.col.f32.tf32.tf32.f32 "
        "{%0,%1,%2,%3}, {%4,%5,%6,%7}, {%8,%9}, {%0,%1,%2,%3};"
        : "+f"(c[0]), "+f"(c[1]), "+f"(c[2]), "+f"(c[3])
        : "r"(a[0]), "r"(a[1]), "r"(a[2]), "r"(a[3]), "r"(b[0]), "r"(b[1]));
}

// Shared tile: 128 rows x 32 fp32, padded stride 40 floats
#define TSTRIDE 40
#define TILE_WORDS (128 * TSTRIDE)
#define TILE_BYTES (TILE_WORDS * 4)
#define SMEM_GEMM  (4 * TILE_BYTES)      // 2 stages x (A + B) = 81920 B

// Async-copy one 128x32 fp32 tile into smem (raw bits).
__device__ __forceinline__ void cp_tile(
    uint32_t sdst, const float* __restrict__ src, int ld, int r0, int k0, int tid)
{
#pragma unroll
    for (int it = 0; it < 4; it++) {
        int s = tid + it * 256;
        int r = s >> 3, c4 = (s & 7) * 4;
        uint32_t d = sdst + (uint32_t)(r * TSTRIDE + c4) * 4;
        const float* g = &src[(size_t)(r0 + r) * ld + k0 + c4];
        asm volatile("cp.async.ca.shared.global [%0], [%1], 16;" :: "r"(d), "l"(g));
    }
}
#define CP_COMMIT() asm volatile("cp.async.commit_group;" ::: "memory")
#define CP_WAIT(n)  asm volatile("cp.async.wait_group %0;" :: "n"(n) : "memory")

// acc[2][8][4] += A-frag x B-frag over one 32-wide K chunk (tf32 RN convert here)
__device__ __forceinline__ void tile_mma(
    float (*acc)[8][4], const uint32_t* As, const uint32_t* Bs,
    int wm, int wn, int lane)
{
#pragma unroll
    for (int kk = 0; kk < 4; kk++) {
        uint32_t a[2][4], b[8][2];
        int kA = kk * 8 + (lane & 3);
#pragma unroll
        for (int mt = 0; mt < 2; mt++) {
            int mr = wm * 32 + mt * 16 + (lane >> 2);
            a[mt][0] = f2tf(__uint_as_float(As[mr * TSTRIDE + kA]));
            a[mt][1] = f2tf(__uint_as_float(As[(mr + 8) * TSTRIDE + kA]));
            a[mt][2] = f2tf(__uint_as_float(As[mr * TSTRIDE + kA + 4]));
            a[mt][3] = f2tf(__uint_as_float(As[(mr + 8) * TSTRIDE + kA + 4]));
        }
#pragma unroll
        for (int nt = 0; nt < 8; nt++) {
            int nc = wn * 64 + nt * 8 + (lane >> 2);
            b[nt][0] = f2tf(__uint_as_float(Bs[nc * TSTRIDE + kA]));
            b[nt][1] = f2tf(__uint_as_float(Bs[nc * TSTRIDE + kA + 4]));
        }
#pragma unroll
        for (int nt = 0; nt < 8; nt++)
#pragma unroll
            for (int mt = 0; mt < 2; mt++)
                mma16n8k8(acc[mt][nt], a[mt], b[nt]);
    }
}

// Shared pipelined mainloop body. Returns with acc filled.
__device__ __forceinline__ void mma_mainloop(
    float (*acc)[8][4],
    const float* __restrict__ A, int lda,
    const float* __restrict__ Bt, int ldb,
    int row0, int col0, int K,
    uint32_t sbase, const uint32_t* dyn, int tid, int wm, int wn, int lane)
{
    const uint32_t aOff[2] = { 0, 2 * TILE_BYTES };
    const uint32_t bOff[2] = { TILE_BYTES, 3 * TILE_BYTES };
    cp_tile(sbase + aOff[0], A, lda, row0, 0, tid);
    cp_tile(sbase + bOff[0], Bt, ldb, col0, 0, tid);
    CP_COMMIT();
    int nk = K / 32;
    for (int s = 0; s < nk; s++) {
        int buf = s & 1;
        if (s + 1 < nk) {
            cp_tile(sbase + aOff[buf ^ 1], A, lda, row0, (s + 1) * 32, tid);
            cp_tile(sbase + bOff[buf ^ 1], Bt, ldb, col0, (s + 1) * 32, tid);
            CP_COMMIT();
            CP_WAIT(1);
        } else {
            CP_WAIT(0);
        }
        __syncthreads();
        tile_mma(acc, dyn + buf * 2 * TILE_WORDS, dyn + buf * 2 * TILE_WORDS + TILE_WORDS,
                 wm, wn, lane);
        __syncthreads();
    }
}

// ---------------------------------------------------------------------------
// Generic GEMM: C[M,N] = A[M,K] @ Bt[N,K]^T
// ---------------------------------------------------------------------------
__global__ __launch_bounds__(256) void gemm_mma_kernel(
    const float* __restrict__ A, int lda,
    const float* __restrict__ Bt, int ldb,
    float* __restrict__ C, int ldc, int K)
{
    extern __shared__ uint32_t dyn[];
    uint32_t sbase = smem_u32(dyn);
    int tid = threadIdx.x;
    int wid = tid >> 5, lane = tid & 31;
    int wm = wid & 3, wn = wid >> 2;
    int row0 = blockIdx.y * 128, col0 = blockIdx.x * 128;

    float acc[2][8][4];
#pragma unroll
    for (int mt = 0; mt < 2; mt++)
#pragma unroll
        for (int nt = 0; nt < 8; nt++)
#pragma unroll
            for (int e = 0; e < 4; e++) acc[mt][nt][e] = 0.f;

    mma_mainloop(acc, A, lda, Bt, ldb, row0, col0, K, sbase, dyn, tid, wm, wn, lane);

#pragma unroll
    for (int mt = 0; mt < 2; mt++) {
        int r0 = row0 + wm * 32 + mt * 16 + (lane >> 2);
#pragma unroll
        for (int nt = 0; nt < 8; nt++) {
            int c = col0 + wn * 64 + nt * 8 + (lane & 3) * 2;
            *reinterpret_cast<float2*>(&C[(size_t)r0 * ldc + c]) =
                make_float2(acc[mt][nt][0], acc[mt][nt][1]);
            *reinterpret_cast<float2*>(&C[(size_t)(r0 + 8) * ldc + c]) =
                make_float2(acc[mt][nt][2], acc[mt][nt][3]);
        }
    }
}

// ---------------------------------------------------------------------------
// Causal scores: logits[h][i][j] = (q_i.k_j)*SCALE for j<=i else -3e38
// ---------------------------------------------------------------------------
__global__ __launch_bounds__(256) void scores_mma_kernel(
    const float* __restrict__ q, const float* __restrict__ k)
{
    int jt = blockIdx.x, it = blockIdx.y, h = blockIdx.z;
    if (jt > it) return;

    extern __shared__ uint32_t dyn[];
    uint32_t sbase = smem_u32(dyn);
    int tid = threadIdx.x;
    int wid = tid >> 5, lane = tid & 31;
    int wm = wid & 3, wn = wid >> 2;
    int row0 = it * 128, col0 = jt * 128;

    const float* Aq = q + h * Dv;
    const float* Bk = k + (h >> 2) * Dv;

    float acc[2][8][4];
#pragma unroll
    for (int mt = 0; mt < 2; mt++)
#pragma unroll
        for (int nt = 0; nt < 8; nt++)
#pragma unroll
            for (int e = 0; e < 4; e++) acc[mt][nt][e] = 0.f;

    mma_mainloop(acc, Aq, QKV, Bk, QKV, row0, col0, Dv, sbase, dyn, tid, wm, wn, lane);

#pragma unroll
    for (int mt = 0; mt < 2; mt++) {
        int r0 = row0 + wm * 32 + mt * 16 + (lane >> 2);
#pragma unroll
        for (int nt = 0; nt < 8; nt++) {
            int c = col0 + wn * 64 + nt * 8 + (lane & 3) * 2;
            float2 v0, v1;
            v0.x = (c + 0 <= r0) ? acc[mt][nt][0] * SCALE : -3.0e38f;
            v0.y = (c + 1 <= r0) ? acc[mt][nt][1] * SCALE : -3.0e38f;
            v1.x = (c + 0 <= r0 + 8) ? acc[mt][nt][2] * SCALE : -3.0e38f;
            v1.y = (c + 1 <= r0 + 8) ? acc[mt][nt][3] * SCALE : -3.0e38f;
            *reinterpret_cast<float2*>(&g_scores[((size_t)h * Sq + r0) * Sq + c]) = v0;
            *reinterpret_cast<float2*>(&g_scores[((size_t)h * Sq + r0 + 8) * Sq + c]) = v1;
        }
    }
}

// ---------------------------------------------------------------------------
// Weight transpose: W[K,N] -> Wt[N,K]
// ---------------------------------------------------------------------------
__global__ void transpose_kernel(const float* __restrict__ W, float* __restrict__ Wt,
                                 int K, int N)
{
    __shared__ float t[32][33];
    int n0 = blockIdx.x * 32, k0 = blockIdx.y * 32;
    int tx = threadIdx.x, ty = threadIdx.y;  // 32 x 8
#pragma unroll
    for (int i = 0; i < 4; i++)
        t[ty + i * 8][tx] = W[(size_t)(k0 + ty + i * 8) * N + n0 + tx];
    __syncthreads();
#pragma unroll
    for (int i = 0; i < 4; i++)
        Wt[(size_t)(n0 + ty + i * 8) * K + k0 + tx] = t[tx][ty + i * 8];
}

// ---------------------------------------------------------------------------
// RoPE in place. x rows of length ld; head h occupies cols h*128..h*128+127.
// ---------------------------------------------------------------------------
__global__ void rope_kernel(float* x, int H, int ld)
{
    int idx = blockIdx.x * blockDim.x + threadIdx.x;
    int total = Sq * H * 64;
    if (idx >= total) return;
    int j = idx & 63;
    int t = idx >> 6;
    int h = t % H;
    int s = t / H;
    float inv = powf(10000.0f, -(float)(2 * j) / 128.0f);
    float f = (float)s * inv;
    double fd = (double)f;
    float c = (float)cos(fd);
    float sn = (float)sin(fd);
    size_t base = (size_t)s * ld + h * 128;
    float x1 = x[base + j], x2 = x[base + 64 + j];
    x[base + j]      = x1 * c - x2 * sn;
    x[base + 64 + j] = x2 * c + x1 * sn;
}

// ---------------------------------------------------------------------------
// Row pass: compute max over j<=i, overwrite logits with unnormalized probs
// exp(x - m), store row sum. ONE exp per score element total.
// ---------------------------------------------------------------------------
__global__ __launch_bounds__(256) void rowprob_kernel()
{
    int i = blockIdx.x, h = blockIdx.y;
    float* row = &g_scores[((size_t)h * Sq + i) * Sq];
    int n = i + 1;
    __shared__ float red[256];
    int tid = threadIdx.x;

    float m = -3.4e38f;
    for (int j = tid; j < n; j += 256) m = fmaxf(m, row[j]);
    red[tid] = m; __syncthreads();
    for (int w = 128; w > 0; w >>= 1) {
        if (tid < w) red[tid] = fmaxf(red[tid], red[tid + w]);
        __syncthreads();
    }
    m = red[0]; __syncthreads();

    float sum = 0.f;
    for (int j = tid; j < n; j += 256) {
        float p = __expf(row[j] - m);
        row[j] = p;
        sum += p;
    }
    red[tid] = sum; __syncthreads();
    for (int w = 128; w > 0; w >>= 1) {
        if (tid < w) red[tid] += red[tid + w];
        __syncthreads();
    }
    if (tid == 0) g_rowsum[h * Sq + i] = red[0];
}

// ---------------------------------------------------------------------------
// Column-sum of normalized probs: partial sums per 16-row chunk. No exp.
// ---------------------------------------------------------------------------
__global__ __launch_bounds__(256) void colsum_kernel()
{
    int chunk = blockIdx.x, h = blockIdx.y;
    int i0 = chunk * 16;
    __shared__ float cs[2048];
    int tid = threadIdx.x;
    for (int j = tid; j < Sq; j += 256) cs[j] = 0.f;
    __syncthreads();
    for (int r = 0; r < 16; r++) {
        int i = i0 + r;
        float invl = 1.0f / g_rowsum[h * Sq + i];
        const float* row = &g_scores[((size_t)h * Sq + i) * Sq];
        for (int j = tid; j <= i; j += 256) cs[j] += row[j] * invl;
    }
    __syncthreads();
    float* dst = &g_colpart[((size_t)h * 128 + chunk) * Sq];
    for (int j = tid; j < Sq; j += 256) dst[j] = cs[j];
}

__global__ void colreduce_kernel()
{
    int j = blockIdx.x * 256 + threadIdx.x;
    int h = blockIdx.y;
    float s = 0.f;
    for (int c = 0; c < 128; c++) s += g_colpart[((size_t)h * 128 + c) * Sq + j];
    g_colsum[h * Sq + j] = s;
}

// ---------------------------------------------------------------------------
// Top-204 per head via bitonic sort (descending) + deterministic index build.
// ---------------------------------------------------------------------------
__global__ __launch_bounds__(1024) void topk_kernel()
{
    int h = blockIdx.x;
    __shared__ float sorted[2048];
    int tid = threadIdx.x;
    for (int j = tid; j < Sq; j += 1024) sorted[j] = g_colsum[h * Sq + j];
    __syncthreads();

    for (int kk = 2; kk <= 2048; kk <<= 1) {
        for (int jj = kk >> 1; jj > 0; jj >>= 1) {
            for (int t = tid; t < 2048; t += 1024) {
                int ixj = t ^ jj;
                if (ixj > t) {
                    float a = sorted[t], b = sorted[ixj];
                    bool desc = ((t & kk) == 0);
                    bool sw = desc ? (a < b) : (a > b);
                    if (sw) { sorted[t] = b; sorted[ixj] = a; }
                }
            }
            __syncthreads();
        }
    }
    float thresh = sorted[HBv - 1];
    if (tid == 0) {
        int cnt = 0;
        for (int j = 0; j < Sq && cnt < HBv; j++)
            if (g_colsum[h * Sq + j] > thresh) g_heavy_idx[h * HBv + cnt++] = j;
        for (int j = 0; j < Sq && cnt < HBv; j++)
            if (g_colsum[h * Sq + j] == thresh) g_heavy_idx[h * HBv + cnt++] = j;
    }
}

// ---------------------------------------------------------------------------
// Final sparse attention on stored probs: out = sum(p*v) / sum(p) over kept.
// ---------------------------------------------------------------------------
__global__ __launch_bounds__(256) void attnout_kernel(const float* __restrict__ v, int ldv)
{
    int i = blockIdx.x, h = blockIdx.y;
    int kv = h / GRP;
    int tid = threadIdx.x;
    __shared__ int jlist[512];
    __shared__ float pv[512];
    __shared__ float red[256];
    __shared__ int n_s;

    int lo = i - RBv; if (lo < 0) lo = 0;
    int nb = i - lo + 1;
    for (int t = tid; t < nb; t += 256) jlist[t] = lo + t;
    if (tid == 0) {
        int cnt = nb;
        for (int t = 0; t < HBv; t++) {
            int j = g_heavy_idx[h * HBv + t];
            if (j < lo) jlist[cnt++] = j;
        }
        n_s = cnt;
    }
    __syncthreads();
    int n = n_s;
    const float* row = &g_scores[((size_t)h * Sq + i) * Sq];

    float sum = 0.f;
    for (int t = tid; t < n; t += 256) {
        float p = row[jlist[t]];
        pv[t] = p;
        sum += p;
    }
    red[tid] = sum; __syncthreads();
    for (int w = 128; w > 0; w >>= 1) {
        if (tid < w) red[tid] += red[tid + w];
        __syncthreads();
    }
    float invl = 1.0f / red[0];
    __syncthreads();

    int d = tid & 127;
    int half = tid >> 7;
    float acc = 0.f;
    for (int t = half; t < n; t += 2)
        acc += pv[t] * v[(size_t)jlist[t] * ldv + kv * Dv + d];
    red[tid] = acc; __syncthreads();
    if (tid < 128)
        g_attnout[(size_t)i * HIDv + h * Dv + tid] = (red[tid] + red[tid + 128]) * invl;
}

// ---------------------------------------------------------------------------
extern "C" void kernel_launch(void* const* d_in, const int* in_sizes, int n_in,
                              void* d_out, int out_size)
{
    const float* hs = (const float*)d_in[0];
    const float* Wq = (const float*)d_in[1];
    const float* Wk = (const float*)d_in[2];
    const float* Wv = (const float*)d_in[3];
    const float* Wo = (const float*)d_in[4];
    float* out = (float*)d_out;

    void* p;
    cudaGetSymbolAddress(&p, g_qkv);     float* qkv = (float*)p;
    cudaGetSymbolAddress(&p, g_wt);      float* wt  = (float*)p;
    cudaGetSymbolAddress(&p, g_attnout); float* aop = (float*)p;

    cudaFuncSetAttribute(gemm_mma_kernel,
                         cudaFuncAttributeMaxDynamicSharedMemorySize, SMEM_GEMM);
    cudaFuncSetAttribute(scores_mma_kernel,
                         cudaFuncAttributeMaxDynamicSharedMemorySize, SMEM_GEMM);

    dim3 tb(32, 8);

    // Transpose Wq|Wk|Wv into one K-major [3072, 2048] block
    transpose_kernel<<<dim3(HIDv / 32, HIDv / 32), tb>>>(Wq, wt, HIDv, HIDv);
    transpose_kernel<<<dim3((NKVv * Dv) / 32, HIDv / 32), tb>>>(
        Wk, wt + (size_t)2048 * HIDv, HIDv, NKVv * Dv);
    transpose_kernel<<<dim3((NKVv * Dv) / 32, HIDv / 32), tb>>>(
        Wv, wt + (size_t)2560 * HIDv, HIDv, NKVv * Dv);

    // Fused QKV projection: [2048, 2048] @ [3072, 2048]^T -> [2048, 3072]
    gemm_mma_kernel<<<dim3(QKV / 128, Sq / 128), 256, SMEM_GEMM>>>(
        hs, HIDv, wt, HIDv, qkv, QKV, HIDv);

    // RoPE on q (16 heads) and k (4 heads)
    rope_kernel<<<(Sq * NHv * 64 + 255) / 256, 256>>>(qkv, NHv, QKV);
    rope_kernel<<<(Sq * NKVv * 64 + 255) / 256, 256>>>(qkv + 2048, NKVv, QKV);

    // Causal scores
    scores_mma_kernel<<<dim3(Sq / 128, Sq / 128, NHv), 256, SMEM_GEMM>>>(
        qkv, qkv + 2048);

    // Softmax -> probs in place (single exp pass), then oracle
    rowprob_kernel<<<dim3(Sq, NHv), 256>>>();
    colsum_kernel<<<dim3(Sq / 16, NHv), 256>>>();
    colreduce_kernel<<<dim3(Sq / 256, NHv), 256>>>();
    topk_kernel<<<NHv, 1024>>>();

    // Sparse attention output from stored probs
    attnout_kernel<<<dim3(Sq, NHv), 256>>>(qkv + 2560, QKV);

    // Output projection
    transpose_kernel<<<dim3(HIDv / 32, HIDv / 32), tb>>>(Wo, wt, HIDv, HIDv);
    gemm_mma_kernel<<<dim3(HIDv / 128, Sq / 128), 256, SMEM_GEMM>>>(
        aop, HIDv, wt, HIDv, out, HIDv, HIDv);
}

// round 5
// speedup vs baseline: 3.2640x; 1.8477x over previous
#include <cuda_runtime.h>
#include <cuda_fp16.h>
#include <math.h>
#include <stdint.h>

// Problem constants
static const int Sq   = 2048;
static const int HIDv = 2048;
static const int NHv  = 16;
static const int NKVv = 4;
static const int Dv   = 128;
static const int GRP  = 4;
static const int HBv  = 204;
static const int RBv  = 204;
static const int QKV  = 3072;
#define SCALE 0.08838834764831845f  // 1/sqrt(128)

// Scratch (device globals; allocation-free)
__device__ __half g_hs16[2048 * 2048];
__device__ __half g_wt16[3072 * 2048];
__device__ float  g_qkv[2048 * 3072];                // fp32 q|k|v (rope + v source)
__device__ __half g_q16[2048 * 2048];
__device__ __half g_k16[2048 * 512];
__device__ __half g_attn16[2048 * 2048];
__device__ float  g_scores[16LL * 2048 * 2048];      // logits then probs
__device__ float  g_rowsum[16 * 2048];
__device__ float  g_colpart[16 * 128 * 2048];
__device__ float  g_colsum[16 * 2048];
__device__ int    g_heavy_idx[16 * 204];

// ===========================================================================
// fp16 mma.sync GEMM machinery (baseline sm_100 PTX)
// ===========================================================================
__device__ __forceinline__ uint32_t smem_u32(const void* p) {
    uint32_t a;
    asm("{ .reg .u64 t; cvta.to.shared.u64 t, %1; cvt.u32.u64 %0, t; }" : "=r"(a) : "l"(p));
    return a;
}
__device__ __forceinline__ void mma_h(float* c, const uint32_t* a, const uint32_t* b) {
    asm volatile(
        "mma.sync.aligned.m16n8k16.row.col.f32.f16.f16.f32 "
        "{%0,%1,%2,%3}, {%4,%5,%6,%7}, {%8,%9}, {%0,%1,%2,%3};"
        : "+f"(c[0]), "+f"(c[1]), "+f"(c[2]), "+f"(c[3])
        : "r"(a[0]), "r"(a[1]), "r"(a[2]), "r"(a[3]), "r"(b[0]), "r"(b[1]));
}

// Tile: 128 rows x 64 halfs, padded row stride 72 halfs (36 words, 144 B)
#define PADW 36
#define TILEH_BYTES (128 * 144)
#define SMEM_H (4 * TILEH_BYTES)   // 2 stages x (A + B) = 73728 B

__device__ __forceinline__ void cp_tile_h(
    uint32_t sdst, const __half* __restrict__ src, int ld, int r0, int k0, int tid)
{
#pragma unroll
    for (int it = 0; it < 4; it++) {
        int s = tid + it * 256;
        int r = s >> 3, c8 = (s & 7) * 8;
        uint32_t d = sdst + (uint32_t)(r * 144 + c8 * 2);
        const __half* g = &src[(size_t)(r0 + r) * ld + k0 + c8];
        asm volatile("cp.async.ca.shared.global [%0], [%1], 16;" :: "r"(d), "l"(g));
    }
}
#define CP_COMMIT() asm volatile("cp.async.commit_group;" ::: "memory")
#define CP_WAIT(n)  asm volatile("cp.async.wait_group %0;" :: "n"(n) : "memory")

// acc[2][8][4] += A x B^T over one 64-half K chunk (4 x m16n8k16)
__device__ __forceinline__ void tile_mma_h(
    float (*acc)[8][4], const uint32_t* As, const uint32_t* Bs,
    int wm, int wn, int lane)
{
#pragma unroll
    for (int kk = 0; kk < 4; kk++) {
        int kw = kk * 8 + (lane & 3);
        uint32_t a[2][4], b[8][2];
#pragma unroll
        for (int mt = 0; mt < 2; mt++) {
            int mr = wm * 32 + mt * 16 + (lane >> 2);
            a[mt][0] = As[mr * PADW + kw];
            a[mt][1] = As[(mr + 8) * PADW + kw];
            a[mt][2] = As[mr * PADW + kw + 4];
            a[mt][3] = As[(mr + 8) * PADW + kw + 4];
        }
#pragma unroll
        for (int nt = 0; nt < 8; nt++) {
            int nc = wn * 64 + nt * 8 + (lane >> 2);
            b[nt][0] = Bs[nc * PADW + kw];
            b[nt][1] = Bs[nc * PADW + kw + 4];
        }
#pragma unroll
        for (int nt = 0; nt < 8; nt++)
#pragma unroll
            for (int mt = 0; mt < 2; mt++)
                mma_h(acc[mt][nt], a[mt], b[nt]);
    }
}

__device__ __forceinline__ void mainloop_h(
    float (*acc)[8][4],
    const __half* __restrict__ A, int lda,
    const __half* __restrict__ Bt, int ldb,
    int row0, int col0, int K,
    uint32_t sbase, const uint32_t* dyn, int tid, int wm, int wn, int lane)
{
    const uint32_t aOff[2] = { 0, 2 * TILEH_BYTES };
    const uint32_t bOff[2] = { TILEH_BYTES, 3 * TILEH_BYTES };
    cp_tile_h(sbase + aOff[0], A, lda, row0, 0, tid);
    cp_tile_h(sbase + bOff[0], Bt, ldb, col0, 0, tid);
    CP_COMMIT();
    int nk = K / 64;
    for (int s = 0; s < nk; s++) {
        int buf = s & 1;
        if (s + 1 < nk) {
            cp_tile_h(sbase + aOff[buf ^ 1], A, lda, row0, (s + 1) * 64, tid);
            cp_tile_h(sbase + bOff[buf ^ 1], Bt, ldb, col0, (s + 1) * 64, tid);
            CP_COMMIT();
            CP_WAIT(1);
        } else {
            CP_WAIT(0);
        }
        __syncthreads();
        tile_mma_h(acc, dyn + (aOff[buf] >> 2), dyn + (bOff[buf] >> 2), wm, wn, lane);
        __syncthreads();
    }
}

// ---------------------------------------------------------------------------
// Generic GEMM: C[M,N](fp32) = A[M,K](fp16) @ Bt[N,K](fp16)^T
// ---------------------------------------------------------------------------
__global__ __launch_bounds__(256) void gemm_h_kernel(
    const __half* __restrict__ A, int lda,
    const __half* __restrict__ Bt, int ldb,
    float* __restrict__ C, int ldc, int K)
{
    extern __shared__ uint32_t dyn[];
    uint32_t sbase = smem_u32(dyn);
    int tid = threadIdx.x;
    int wid = tid >> 5, lane = tid & 31;
    int wm = wid & 3, wn = wid >> 2;
    int row0 = blockIdx.y * 128, col0 = blockIdx.x * 128;

    float acc[2][8][4];
#pragma unroll
    for (int mt = 0; mt < 2; mt++)
#pragma unroll
        for (int nt = 0; nt < 8; nt++)
#pragma unroll
            for (int e = 0; e < 4; e++) acc[mt][nt][e] = 0.f;

    mainloop_h(acc, A, lda, Bt, ldb, row0, col0, K, sbase, dyn, tid, wm, wn, lane);

#pragma unroll
    for (int mt = 0; mt < 2; mt++) {
        int r0 = row0 + wm * 32 + mt * 16 + (lane >> 2);
#pragma unroll
        for (int nt = 0; nt < 8; nt++) {
            int c = col0 + wn * 64 + nt * 8 + (lane & 3) * 2;
            *reinterpret_cast<float2*>(&C[(size_t)r0 * ldc + c]) =
                make_float2(acc[mt][nt][0], acc[mt][nt][1]);
            *reinterpret_cast<float2*>(&C[(size_t)(r0 + 8) * ldc + c]) =
                make_float2(acc[mt][nt][2], acc[mt][nt][3]);
        }
    }
}

// ---------------------------------------------------------------------------
// Causal scores: logits[h][i][j] = (q_i.k_j)*SCALE for j<=i else -3e38
// ---------------------------------------------------------------------------
__global__ __launch_bounds__(256) void scores_h_kernel(
    const __half* __restrict__ q, const __half* __restrict__ k)
{
    int jt = blockIdx.x, it = blockIdx.y, h = blockIdx.z;
    if (jt > it) return;

    extern __shared__ uint32_t dyn[];
    uint32_t sbase = smem_u32(dyn);
    int tid = threadIdx.x;
    int wid = tid >> 5, lane = tid & 31;
    int wm = wid & 3, wn = wid >> 2;
    int row0 = it * 128, col0 = jt * 128;

    const __half* Aq = q + h * Dv;
    const __half* Bk = k + (h >> 2) * Dv;

    float acc[2][8][4];
#pragma unroll
    for (int mt = 0; mt < 2; mt++)
#pragma unroll
        for (int nt = 0; nt < 8; nt++)
#pragma unroll
            for (int e = 0; e < 4; e++) acc[mt][nt][e] = 0.f;

    mainloop_h(acc, Aq, HIDv, Bk, NKVv * Dv, row0, col0, Dv, sbase, dyn, tid, wm, wn, lane);

#pragma unroll
    for (int mt = 0; mt < 2; mt++) {
        int r0 = row0 + wm * 32 + mt * 16 + (lane >> 2);
#pragma unroll
        for (int nt = 0; nt < 8; nt++) {
            int c = col0 + wn * 64 + nt * 8 + (lane & 3) * 2;
            float2 v0, v1;
            v0.x = (c + 0 <= r0) ? acc[mt][nt][0] * SCALE : -3.0e38f;
            v0.y = (c + 1 <= r0) ? acc[mt][nt][1] * SCALE : -3.0e38f;
            v1.x = (c + 0 <= r0 + 8) ? acc[mt][nt][2] * SCALE : -3.0e38f;
            v1.y = (c + 1 <= r0 + 8) ? acc[mt][nt][3] * SCALE : -3.0e38f;
            *reinterpret_cast<float2*>(&g_scores[((size_t)h * Sq + r0) * Sq + c]) = v0;
            *reinterpret_cast<float2*>(&g_scores[((size_t)h * Sq + r0 + 8) * Sq + c]) = v1;
        }
    }
}

// ---------------------------------------------------------------------------
// Elementwise fp32 -> fp16
// ---------------------------------------------------------------------------
__global__ void f2h_kernel(const float* __restrict__ in, __half* __restrict__ out, int n4)
{
    int i = blockIdx.x * blockDim.x + threadIdx.x;
    if (i >= n4) return;
    float4 v = reinterpret_cast<const float4*>(in)[i];
    __half2 lo = __floats2half2_rn(v.x, v.y);
    __half2 hi = __floats2half2_rn(v.z, v.w);
    reinterpret_cast<__half2*>(out)[i * 2]     = lo;
    reinterpret_cast<__half2*>(out)[i * 2 + 1] = hi;
}

// ---------------------------------------------------------------------------
// Weight transpose to fp16: W[K,N](f32) -> Wt[N,K](f16)
// ---------------------------------------------------------------------------
__global__ void transpose_h_kernel(const float* __restrict__ W, __half* __restrict__ Wt,
                                   int K, int N)
{
    __shared__ float t[32][33];
    int n0 = blockIdx.x * 32, k0 = blockIdx.y * 32;
    int tx = threadIdx.x, ty = threadIdx.y;  // 32 x 8
#pragma unroll
    for (int i = 0; i < 4; i++)
        t[ty + i * 8][tx] = W[(size_t)(k0 + ty + i * 8) * N + n0 + tx];
    __syncthreads();
#pragma unroll
    for (int i = 0; i < 4; i++)
        Wt[(size_t)(n0 + ty + i * 8) * K + k0 + tx] = __float2half_rn(t[tx][ty + i * 8]);
}

// ---------------------------------------------------------------------------
// RoPE: read fp32 from g_qkv (ld 3072), write rotated fp16.
// ---------------------------------------------------------------------------
__global__ void rope_h_kernel(const float* __restrict__ in, int in_off,
                              __half* __restrict__ out, int H, int out_ld)
{
    int idx = blockIdx.x * blockDim.x + threadIdx.x;
    int total = Sq * H * 64;
    if (idx >= total) return;
    int j = idx & 63;
    int t = idx >> 6;
    int h = t % H;
    int s = t / H;
    float inv = powf(10000.0f, -(float)(2 * j) / 128.0f);
    float f = (float)s * inv;
    double fd = (double)f;
    float c = (float)cos(fd);
    float sn = (float)sin(fd);
    size_t bi = (size_t)s * QKV + in_off + h * 128;
    float x1 = in[bi + j], x2 = in[bi + 64 + j];
    size_t bo = (size_t)s * out_ld + h * 128;
    out[bo + j]      = __float2half_rn(x1 * c - x2 * sn);
    out[bo + 64 + j] = __float2half_rn(x2 * c + x1 * sn);
}

// ---------------------------------------------------------------------------
// Row pass: max over j<=i, overwrite with unnormalized probs, store row sum.
// ---------------------------------------------------------------------------
__global__ __launch_bounds__(256) void rowprob_kernel()
{
    int i = blockIdx.x, h = blockIdx.y;
    float* row = &g_scores[((size_t)h * Sq + i) * Sq];
    int n = i + 1;
    __shared__ float red[256];
    int tid = threadIdx.x;

    float m = -3.4e38f;
    for (int j = tid; j < n; j += 256) m = fmaxf(m, row[j]);
    red[tid] = m; __syncthreads();
    for (int w = 128; w > 0; w >>= 1) {
        if (tid < w) red[tid] = fmaxf(red[tid], red[tid + w]);
        __syncthreads();
    }
    m = red[0]; __syncthreads();

    float sum = 0.f;
    for (int j = tid; j < n; j += 256) {
        float p = __expf(row[j] - m);
        row[j] = p;
        sum += p;
    }
    red[tid] = sum; __syncthreads();
    for (int w = 128; w > 0; w >>= 1) {
        if (tid < w) red[tid] += red[tid + w];
        __syncthreads();
    }
    if (tid == 0) g_rowsum[h * Sq + i] = red[0];
}

// ---------------------------------------------------------------------------
// Column-sum of normalized probs, per 16-row chunk.
// ---------------------------------------------------------------------------
__global__ __launch_bounds__(256) void colsum_kernel()
{
    int chunk = blockIdx.x, h = blockIdx.y;
    int i0 = chunk * 16;
    __shared__ float cs[2048];
    int tid = threadIdx.x;
    for (int j = tid; j < Sq; j += 256) cs[j] = 0.f;
    __syncthreads();
    for (int r = 0; r < 16; r++) {
        int i = i0 + r;
        float invl = 1.0f / g_rowsum[h * Sq + i];
        const float* row = &g_scores[((size_t)h * Sq + i) * Sq];
        for (int j = tid; j <= i; j += 256) cs[j] += row[j] * invl;
    }
    __syncthreads();
    float* dst = &g_colpart[((size_t)h * 128 + chunk) * Sq];
    for (int j = tid; j < Sq; j += 256) dst[j] = cs[j];
}

__global__ void colreduce_kernel()
{
    int j = blockIdx.x * 256 + threadIdx.x;
    int h = blockIdx.y;
    float s = 0.f;
    for (int c = 0; c < 128; c++) s += g_colpart[((size_t)h * 128 + c) * Sq + j];
    g_colsum[h * Sq + j] = s;
}

// ---------------------------------------------------------------------------
// Top-204 per head via bitonic sort + deterministic index build.
// ---------------------------------------------------------------------------
__global__ __launch_bounds__(1024) void topk_kernel()
{
    int h = blockIdx.x;
    __shared__ float sorted[2048];
    int tid = threadIdx.x;
    for (int j = tid; j < Sq; j += 1024) sorted[j] = g_colsum[h * Sq + j];
    __syncthreads();

    for (int kk = 2; kk <= 2048; kk <<= 1) {
        for (int jj = kk >> 1; jj > 0; jj >>= 1) {
            for (int t = tid; t < 2048; t += 1024) {
                int ixj = t ^ jj;
                if (ixj > t) {
                    float a = sorted[t], b = sorted[ixj];
                    bool desc = ((t & kk) == 0);
                    bool sw = desc ? (a < b) : (a > b);
                    if (sw) { sorted[t] = b; sorted[ixj] = a; }
                }
            }
            __syncthreads();
        }
    }
    float thresh = sorted[HBv - 1];
    if (tid == 0) {
        int cnt = 0;
        for (int j = 0; j < Sq && cnt < HBv; j++)
            if (g_colsum[h * Sq + j] > thresh) g_heavy_idx[h * HBv + cnt++] = j;
        for (int j = 0; j < Sq && cnt < HBv; j++)
            if (g_colsum[h * Sq + j] == thresh) g_heavy_idx[h * HBv + cnt++] = j;
    }
}

// ---------------------------------------------------------------------------
// Sparse attention: block = (16-query tile, head). Kept superset (<=424 cols)
// staged as masked probs in smem; V rows loaded once per tile.
// ---------------------------------------------------------------------------
__global__ __launch_bounds__(256) void attnout2_kernel(const float* __restrict__ v, int ldv)
{
    __shared__ int jl[432];
    __shared__ float ps[432][20];          // [col][query], float4-readable rows
    __shared__ unsigned char wflag[224];
    __shared__ float psum[16];
    __shared__ float part[16][17];
    __shared__ int n_s;

    int h = blockIdx.y;
    int i0 = blockIdx.x * 16;
    int kv = h >> 2;
    int tid = threadIdx.x;

    int lo0 = i0 - RBv; if (lo0 < 0) lo0 = 0;
    int wlen = i0 + 15 - lo0 + 1;          // <= 220
    for (int t = tid; t < 224; t += 256) wflag[t] = 0;
    for (int t = tid; t < wlen; t += 256) jl[t] = lo0 + t;
    __syncthreads();
    if (tid == 0) {
        int cnt = wlen;
        for (int t = 0; t < HBv; t++) {
            int j = g_heavy_idx[h * HBv + t];
            if (j < lo0) jl[cnt++] = j;
            else if (j <= i0 + 15) wflag[j - lo0] = 1;
        }
        n_s = cnt;
    }
    __syncthreads();
    int n = n_s;

    // Masked prob staging: ps[t][q] = p if kept(q, jl[t]) else 0
#pragma unroll 1
    for (int q = 0; q < 16; q++) {
        int iq = i0 + q;
        const float* row = &g_scores[((size_t)h * Sq + iq) * Sq];
        for (int t = tid; t < n; t += 256) {
            int j = jl[t];
            float val = 0.f;
            if (j <= iq) {
                bool kept = (t < wlen) ? (j >= iq - RBv || wflag[t]) : true;
                if (kept) val = row[j];
            }
            ps[t][q] = val;
        }
    }
    __syncthreads();

    // Per-query kept-sum
    {
        int q = tid >> 4, c = tid & 15;
        float s = 0.f;
        for (int t = c; t < n; t += 16) s += ps[t][q];
        part[q][c] = s;
    }
    __syncthreads();
    if (tid < 16) {
        float s = 0.f;
#pragma unroll
        for (int c = 0; c < 16; c++) s += part[tid][c];
        psum[tid] = s;
    }
    __syncthreads();

    // Main: each thread owns dim d (2 threads/dim, split cols even/odd)
    int d = tid & 127, hlf = tid >> 7;
    float acc[16];
#pragma unroll
    for (int q = 0; q < 16; q++) acc[q] = 0.f;
    for (int t = hlf; t < n; t += 2) {
        float vv = v[(size_t)jl[t] * ldv + kv * Dv + d];
        const float4* pr = reinterpret_cast<const float4*>(&ps[t][0]);
#pragma unroll
        for (int qq = 0; qq < 4; qq++) {
            float4 p4 = pr[qq];
            acc[qq * 4 + 0] += p4.x * vv;
            acc[qq * 4 + 1] += p4.y * vv;
            acc[qq * 4 + 2] += p4.z * vv;
            acc[qq * 4 + 3] += p4.w * vv;
        }
    }
    __syncthreads();
    float* comb = &ps[0][0];               // reuse (128*16 floats)
    if (hlf == 1) {
#pragma unroll
        for (int q = 0; q < 16; q++) comb[d * 16 + q] = acc[q];
    }
    __syncthreads();
    if (hlf == 0) {
#pragma unroll
        for (int q = 0; q < 16; q++) {
            float o = (acc[q] + comb[d * 16 + q]) / psum[q];
            g_attn16[(size_t)(i0 + q) * HIDv + h * Dv + d] = __float2half_rn(o);
        }
    }
}

// ---------------------------------------------------------------------------
extern "C" void kernel_launch(void* const* d_in, const int* in_sizes, int n_in,
                              void* d_out, int out_size)
{
    const float* hs = (const float*)d_in[0];
    const float* Wq = (const float*)d_in[1];
    const float* Wk = (const float*)d_in[2];
    const float* Wv = (const float*)d_in[3];
    const float* Wo = (const float*)d_in[4];
    float* out = (float*)d_out;

    void* p;
    cudaGetSymbolAddress(&p, g_hs16);   __half* hs16 = (__half*)p;
    cudaGetSymbolAddress(&p, g_wt16);   __half* wt16 = (__half*)p;
    cudaGetSymbolAddress(&p, g_qkv);    float*  qkv  = (float*)p;
    cudaGetSymbolAddress(&p, g_q16);    __half* q16  = (__half*)p;
    cudaGetSymbolAddress(&p, g_k16);    __half* k16  = (__half*)p;
    cudaGetSymbolAddress(&p, g_attn16); __half* at16 = (__half*)p;

    cudaFuncSetAttribute(gemm_h_kernel,
                         cudaFuncAttributeMaxDynamicSharedMemorySize, SMEM_H);
    cudaFuncSetAttribute(scores_h_kernel,
                         cudaFuncAttributeMaxDynamicSharedMemorySize, SMEM_H);

    dim3 tb(32, 8);

    // Inputs to fp16
    f2h_kernel<<<(2048 * 2048 / 4 + 255) / 256, 256>>>(hs, hs16, 2048 * 2048 / 4);
    transpose_h_kernel<<<dim3(HIDv / 32, HIDv / 32), tb>>>(Wq, wt16, HIDv, HIDv);
    transpose_h_kernel<<<dim3((NKVv * Dv) / 32, HIDv / 32), tb>>>(
        Wk, wt16 + (size_t)2048 * HIDv, HIDv, NKVv * Dv);
    transpose_h_kernel<<<dim3((NKVv * Dv) / 32, HIDv / 32), tb>>>(
        Wv, wt16 + (size_t)2560 * HIDv, HIDv, NKVv * Dv);

    // Fused QKV projection (fp32 out for rope + v)
    gemm_h_kernel<<<dim3(QKV / 128, Sq / 128), 256, SMEM_H>>>(
        hs16, HIDv, wt16, HIDv, qkv, QKV, HIDv);

    // RoPE -> fp16 q/k
    rope_h_kernel<<<(Sq * NHv * 64 + 255) / 256, 256>>>(qkv, 0, q16, NHv, 2048);
    rope_h_kernel<<<(Sq * NKVv * 64 + 255) / 256, 256>>>(qkv, 2048, k16, NKVv, 512);

    // Causal scores
    scores_h_kernel<<<dim3(Sq / 128, Sq / 128, NHv), 256, SMEM_H>>>(q16, k16);

    // Softmax probs in place + H2O oracle
    rowprob_kernel<<<dim3(Sq, NHv), 256>>>();
    colsum_kernel<<<dim3(Sq / 16, NHv), 256>>>();
    colreduce_kernel<<<dim3(Sq / 256, NHv), 256>>>();
    topk_kernel<<<NHv, 1024>>>();

    // Sparse attention (tile-batched, fp32 math, fp16 out)
    attnout2_kernel<<<dim3(Sq / 16, NHv), 256>>>(qkv + 2560, QKV);

    // Output projection
    transpose_h_kernel<<<dim3(HIDv / 32, HIDv / 32), tb>>>(Wo, wt16, HIDv, HIDv);
    gemm_h_kernel<<<dim3(HIDv / 128, Sq / 128), 256, SMEM_H>>>(
        at16, HIDv, wt16, HIDv, out, HIDv, HIDv);
}

// round 6
// speedup vs baseline: 3.6265x; 1.1111x over previous
#include <cuda_runtime.h>
#include <cuda_fp16.h>
#include <math.h>
#include <stdint.h>

// Problem constants
static const int Sq   = 2048;
static const int HIDv = 2048;
static const int NHv  = 16;
static const int NKVv = 4;
static const int Dv   = 128;
static const int GRP  = 4;
static const int HBv  = 204;
static const int RBv  = 204;
static const int QKV  = 3072;
#define SCALE 0.08838834764831845f  // 1/sqrt(128)

// Scratch (device globals; allocation-free)
__device__ __half g_hs16[2048 * 2048];
__device__ __half g_wt16[3072 * 2048];
__device__ float  g_qkv[2048 * 3072];
__device__ __half g_q16[2048 * 2048];
__device__ __half g_k16[2048 * 512];
__device__ __half g_attn16[2048 * 2048];
__device__ float  g_scores[16LL * 2048 * 2048];      // unnormalized probs exp(logit)
__device__ float  g_rspart[16 * 2048 * 16];          // per-(h,row,jt) partial rowsums
__device__ float  g_rowsum[16 * 2048];
__device__ float  g_colpart[16 * 128 * 2048];
__device__ float  g_colsum[16 * 2048];
__device__ int    g_heavy_idx[16 * 204];
__device__ float2 g_trig[2048 * 64];

// ===========================================================================
// fp16 mma.sync GEMM machinery (baseline sm_100 PTX)
// ===========================================================================
__device__ __forceinline__ uint32_t smem_u32(const void* p) {
    uint32_t a;
    asm("{ .reg .u64 t; cvta.to.shared.u64 t, %1; cvt.u32.u64 %0, t; }" : "=r"(a) : "l"(p));
    return a;
}
__device__ __forceinline__ void mma_h(float* c, const uint32_t* a, const uint32_t* b) {
    asm volatile(
        "mma.sync.aligned.m16n8k16.row.col.f32.f16.f16.f32 "
        "{%0,%1,%2,%3}, {%4,%5,%6,%7}, {%8,%9}, {%0,%1,%2,%3};"
        : "+f"(c[0]), "+f"(c[1]), "+f"(c[2]), "+f"(c[3])
        : "r"(a[0]), "r"(a[1]), "r"(a[2]), "r"(a[3]), "r"(b[0]), "r"(b[1]));
}

// Tile: 128 rows x 64 halfs, padded row stride 72 halfs (36 words, 144 B)
#define PADW 36
#define TILEH_BYTES (128 * 144)
#define SMEM_H (4 * TILEH_BYTES)   // 73728 B

__device__ __forceinline__ void cp_tile_h(
    uint32_t sdst, const __half* __restrict__ src, int ld, int r0, int k0, int tid)
{
#pragma unroll
    for (int it = 0; it < 4; it++) {
        int s = tid + it * 256;
        int r = s >> 3, c8 = (s & 7) * 8;
        uint32_t d = sdst + (uint32_t)(r * 144 + c8 * 2);
        const __half* g = &src[(size_t)(r0 + r) * ld + k0 + c8];
        asm volatile("cp.async.ca.shared.global [%0], [%1], 16;" :: "r"(d), "l"(g));
    }
}
#define CP_COMMIT() asm volatile("cp.async.commit_group;" ::: "memory")
#define CP_WAIT(n)  asm volatile("cp.async.wait_group %0;" :: "n"(n) : "memory")

__device__ __forceinline__ void tile_mma_h(
    float (*acc)[8][4], const uint32_t* As, const uint32_t* Bs,
    int wm, int wn, int lane)
{
#pragma unroll
    for (int kk = 0; kk < 4; kk++) {
        int kw = kk * 8 + (lane & 3);
        uint32_t a[2][4], b[8][2];
#pragma unroll
        for (int mt = 0; mt < 2; mt++) {
            int mr = wm * 32 + mt * 16 + (lane >> 2);
            a[mt][0] = As[mr * PADW + kw];
            a[mt][1] = As[(mr + 8) * PADW + kw];
            a[mt][2] = As[mr * PADW + kw + 4];
            a[mt][3] = As[(mr + 8) * PADW + kw + 4];
        }
#pragma unroll
        for (int nt = 0; nt < 8; nt++) {
            int nc = wn * 64 + nt * 8 + (lane >> 2);
            b[nt][0] = Bs[nc * PADW + kw];
            b[nt][1] = Bs[nc * PADW + kw + 4];
        }
#pragma unroll
        for (int nt = 0; nt < 8; nt++)
#pragma unroll
            for (int mt = 0; mt < 2; mt++)
                mma_h(acc[mt][nt], a[mt], b[nt]);
    }
}

__device__ __forceinline__ void mainloop_h(
    float (*acc)[8][4],
    const __half* __restrict__ A, int lda,
    const __half* __restrict__ Bt, int ldb,
    int row0, int col0, int K,
    uint32_t sbase, const uint32_t* dyn, int tid, int wm, int wn, int lane)
{
    const uint32_t aOff[2] = { 0, 2 * TILEH_BYTES };
    const uint32_t bOff[2] = { TILEH_BYTES, 3 * TILEH_BYTES };
    cp_tile_h(sbase + aOff[0], A, lda, row0, 0, tid);
    cp_tile_h(sbase + bOff[0], Bt, ldb, col0, 0, tid);
    CP_COMMIT();
    int nk = K / 64;
    for (int s = 0; s < nk; s++) {
        int buf = s & 1;
        if (s + 1 < nk) {
            cp_tile_h(sbase + aOff[buf ^ 1], A, lda, row0, (s + 1) * 64, tid);
            cp_tile_h(sbase + bOff[buf ^ 1], Bt, ldb, col0, (s + 1) * 64, tid);
            CP_COMMIT();
            CP_WAIT(1);
        } else {
            CP_WAIT(0);
        }
        __syncthreads();
        tile_mma_h(acc, dyn + (aOff[buf] >> 2), dyn + (bOff[buf] >> 2), wm, wn, lane);
        __syncthreads();
    }
}

// ---------------------------------------------------------------------------
// Generic GEMM: C[M,N](fp32) = A[M,K](fp16) @ Bt[N,K](fp16)^T
// ---------------------------------------------------------------------------
__global__ __launch_bounds__(256) void gemm_h_kernel(
    const __half* __restrict__ A, int lda,
    const __half* __restrict__ Bt, int ldb,
    float* __restrict__ C, int ldc, int K)
{
    extern __shared__ uint32_t dyn[];
    uint32_t sbase = smem_u32(dyn);
    int tid = threadIdx.x;
    int wid = tid >> 5, lane = tid & 31;
    int wm = wid & 3, wn = wid >> 2;
    int row0 = blockIdx.y * 128, col0 = blockIdx.x * 128;

    float acc[2][8][4];
#pragma unroll
    for (int mt = 0; mt < 2; mt++)
#pragma unroll
        for (int nt = 0; nt < 8; nt++)
#pragma unroll
            for (int e = 0; e < 4; e++) acc[mt][nt][e] = 0.f;

    mainloop_h(acc, A, lda, Bt, ldb, row0, col0, K, sbase, dyn, tid, wm, wn, lane);

#pragma unroll
    for (int mt = 0; mt < 2; mt++) {
        int r0 = row0 + wm * 32 + mt * 16 + (lane >> 2);
#pragma unroll
        for (int nt = 0; nt < 8; nt++) {
            int c = col0 + wn * 64 + nt * 8 + (lane & 3) * 2;
            *reinterpret_cast<float2*>(&C[(size_t)r0 * ldc + c]) =
                make_float2(acc[mt][nt][0], acc[mt][nt][1]);
            *reinterpret_cast<float2*>(&C[(size_t)(r0 + 8) * ldc + c]) =
                make_float2(acc[mt][nt][2], acc[mt][nt][3]);
        }
    }
}

// ---------------------------------------------------------------------------
// Fast exp: degree-6 Taylor after range reduction, exponent bit-splice.
// Rel err ~1.7e-7 on the active range; clamped below -80.
// ---------------------------------------------------------------------------
__device__ __forceinline__ float poly_exp(float x)
{
    x = fmaxf(x, -80.f);
    float y = x * 1.4426950408889634f;
    float n = rintf(y);
    float f = (y - n) * 0.69314718055994531f;  // |f| <= 0.3466
    float p = 1.f + f * (1.f + f * (0.5f + f * (0.16666667f + f * (0.041666667f +
              f * (0.0083333333f + f * 0.0013888889f)))));
    return __int_as_float(__float_as_int(p) + (((int)n) << 23));
}

// ---------------------------------------------------------------------------
// Causal scores + fused softmax-exp: probs[h][i][j] = exp((q_i.k_j)*SCALE)
// for j<=i else 0. Per-tile row-sum partials -> g_rspart (deterministic).
// Hybrid exp: nt<3 uses FFMA poly, nt>=3 uses MUFU __expf (pipe balance).
// ---------------------------------------------------------------------------
__global__ __launch_bounds__(256) void scores_h_kernel(
    const __half* __restrict__ q, const __half* __restrict__ k)
{
    int jt = blockIdx.x, it = blockIdx.y, h = blockIdx.z;
    if (jt > it) return;

    extern __shared__ uint32_t dyn[];
    __shared__ float srow[2][128];
    uint32_t sbase = smem_u32(dyn);
    int tid = threadIdx.x;
    int wid = tid >> 5, lane = tid & 31;
    int wm = wid & 3, wn = wid >> 2;
    int row0 = it * 128, col0 = jt * 128;

    const __half* Aq = q + h * Dv;
    const __half* Bk = k + (h >> 2) * Dv;

    float acc[2][8][4];
#pragma unroll
    for (int mt = 0; mt < 2; mt++)
#pragma unroll
        for (int nt = 0; nt < 8; nt++)
#pragma unroll
            for (int e = 0; e < 4; e++) acc[mt][nt][e] = 0.f;

    mainloop_h(acc, Aq, HIDv, Bk, NKVv * Dv, row0, col0, Dv, sbase, dyn, tid, wm, wn, lane);

    float rsum[2][2] = {{0.f, 0.f}, {0.f, 0.f}};
#pragma unroll
    for (int mt = 0; mt < 2; mt++) {
        int r = wm * 32 + mt * 16 + (lane >> 2);      // tile-local rows r, r+8
        int gi0 = row0 + r, gi1 = gi0 + 8;
#pragma unroll
        for (int nt = 0; nt < 8; nt++) {
            int c = col0 + wn * 64 + nt * 8 + (lane & 3) * 2;
            float p00 = 0.f, p01 = 0.f, p10 = 0.f, p11 = 0.f;
            if (nt < 3) {
                if (c     <= gi0) p00 = poly_exp(acc[mt][nt][0] * SCALE);
                if (c + 1 <= gi0) p01 = poly_exp(acc[mt][nt][1] * SCALE);
                if (c     <= gi1) p10 = poly_exp(acc[mt][nt][2] * SCALE);
                if (c + 1 <= gi1) p11 = poly_exp(acc[mt][nt][3] * SCALE);
            } else {
                if (c     <= gi0) p00 = __expf(acc[mt][nt][0] * SCALE);
                if (c + 1 <= gi0) p01 = __expf(acc[mt][nt][1] * SCALE);
                if (c     <= gi1) p10 = __expf(acc[mt][nt][2] * SCALE);
                if (c + 1 <= gi1) p11 = __expf(acc[mt][nt][3] * SCALE);
            }
            *reinterpret_cast<float2*>(&g_scores[((size_t)h * Sq + gi0) * Sq + c]) =
                make_float2(p00, p01);
            *reinterpret_cast<float2*>(&g_scores[((size_t)h * Sq + gi1) * Sq + c]) =
                make_float2(p10, p11);
            rsum[mt][0] += p00 + p01;
            rsum[mt][1] += p10 + p11;
        }
    }
    // quad reduce over lane&3 (same rows, different columns)
#pragma unroll
    for (int mt = 0; mt < 2; mt++)
#pragma unroll
        for (int e = 0; e < 2; e++) {
            rsum[mt][e] += __shfl_xor_sync(0xffffffffu, rsum[mt][e], 1);
            rsum[mt][e] += __shfl_xor_sync(0xffffffffu, rsum[mt][e], 2);
        }
    if ((lane & 3) == 0) {
#pragma unroll
        for (int mt = 0; mt < 2; mt++) {
            int r = wm * 32 + mt * 16 + (lane >> 2);
            srow[wn][r]     = rsum[mt][0];
            srow[wn][r + 8] = rsum[mt][1];
        }
    }
    __syncthreads();
    if (tid < 128) {
        float s = srow[0][tid] + srow[1][tid];
        g_rspart[((size_t)h * Sq + row0 + tid) * 16 + jt] = s;
    }
}

// Row-sum partial reduce: sum jt = 0..(i>>7)
__global__ void rowsumred_kernel()
{
    int i = blockIdx.x * 256 + threadIdx.x;
    int h = blockIdx.y;
    int nt = (i >> 7) + 1;
    float s = 0.f;
    for (int t = 0; t < nt; t++) s += g_rspart[((size_t)h * Sq + i) * 16 + t];
    g_rowsum[h * Sq + i] = s;
}

// ---------------------------------------------------------------------------
// Elementwise fp32 -> fp16
// ---------------------------------------------------------------------------
__global__ void f2h_kernel(const float* __restrict__ in, __half* __restrict__ out, int n4)
{
    int i = blockIdx.x * blockDim.x + threadIdx.x;
    if (i >= n4) return;
    float4 v = reinterpret_cast<const float4*>(in)[i];
    reinterpret_cast<__half2*>(out)[i * 2]     = __floats2half2_rn(v.x, v.y);
    reinterpret_cast<__half2*>(out)[i * 2 + 1] = __floats2half2_rn(v.z, v.w);
}

// ---------------------------------------------------------------------------
// Weight transpose to fp16: W[K,N](f32) -> Wt[N,K](f16)
// ---------------------------------------------------------------------------
__global__ void transpose_h_kernel(const float* __restrict__ W, __half* __restrict__ Wt,
                                   int K, int N)
{
    __shared__ float t[32][33];
    int n0 = blockIdx.x * 32, k0 = blockIdx.y * 32;
    int tx = threadIdx.x, ty = threadIdx.y;
#pragma unroll
    for (int i = 0; i < 4; i++)
        t[ty + i * 8][tx] = W[(size_t)(k0 + ty + i * 8) * N + n0 + tx];
    __syncthreads();
#pragma unroll
    for (int i = 0; i < 4; i++)
        Wt[(size_t)(n0 + ty + i * 8) * K + k0 + tx] = __float2half_rn(t[tx][ty + i * 8]);
}

// ---------------------------------------------------------------------------
// RoPE trig table (matches JAX: fp32 freq product, accurate trig on it)
// ---------------------------------------------------------------------------
__global__ void trig_kernel()
{
    int idx = blockIdx.x * 256 + threadIdx.x;   // 131072
    int j = idx & 63;
    int s = idx >> 6;
    float inv = powf(10000.0f, -(float)(2 * j) / 128.0f);
    float f = (float)s * inv;
    double fd = (double)f;
    g_trig[idx] = make_float2((float)cos(fd), (float)sin(fd));
}

__global__ void rope_h_kernel(const float* __restrict__ in, int in_off,
                              __half* __restrict__ out, int H, int out_ld)
{
    int idx = blockIdx.x * blockDim.x + threadIdx.x;
    int total = Sq * H * 64;
    if (idx >= total) return;
    int j = idx & 63;
    int t = idx >> 6;
    int h = t % H;
    int s = t / H;
    float2 cs = g_trig[(s << 6) + j];
    size_t bi = (size_t)s * QKV + in_off + h * 128;
    float x1 = in[bi + j], x2 = in[bi + 64 + j];
    size_t bo = (size_t)s * out_ld + h * 128;
    out[bo + j]      = __float2half_rn(x1 * cs.x - x2 * cs.y);
    out[bo + 64 + j] = __float2half_rn(x2 * cs.x + x1 * cs.y);
}

// ---------------------------------------------------------------------------
// Column-sum of normalized probs, per 16-row chunk. No exp.
// ---------------------------------------------------------------------------
__global__ __launch_bounds__(256) void colsum_kernel()
{
    int chunk = blockIdx.x, h = blockIdx.y;
    int i0 = chunk * 16;
    __shared__ float cs[2048];
    int tid = threadIdx.x;
    for (int j = tid; j < Sq; j += 256) cs[j] = 0.f;
    __syncthreads();
    for (int r = 0; r < 16; r++) {
        int i = i0 + r;
        float invl = 1.0f / g_rowsum[h * Sq + i];
        const float* row = &g_scores[((size_t)h * Sq + i) * Sq];
        for (int j = tid; j <= i; j += 256) cs[j] += row[j] * invl;
    }
    __syncthreads();
    float* dst = &g_colpart[((size_t)h * 128 + chunk) * Sq];
    for (int j = tid; j < Sq; j += 256) dst[j] = cs[j];
}

__global__ void colreduce_kernel()
{
    int j = blockIdx.x * 256 + threadIdx.x;
    int h = blockIdx.y;
    float s = 0.f;
    for (int c = 0; c < 128; c++) s += g_colpart[((size_t)h * 128 + c) * Sq + j];
    g_colsum[h * Sq + j] = s;
}

// ---------------------------------------------------------------------------
// Top-204 per head via bitonic sort + deterministic index build.
// ---------------------------------------------------------------------------
__global__ __launch_bounds__(1024) void topk_kernel()
{
    int h = blockIdx.x;
    __shared__ float sorted[2048];
    int tid = threadIdx.x;
    for (int j = tid; j < Sq; j += 1024) sorted[j] = g_colsum[h * Sq + j];
    __syncthreads();

    for (int kk = 2; kk <= 2048; kk <<= 1) {
        for (int jj = kk >> 1; jj > 0; jj >>= 1) {
            for (int t = tid; t < 2048; t += 1024) {
                int ixj = t ^ jj;
                if (ixj > t) {
                    float a = sorted[t], b = sorted[ixj];
                    bool desc = ((t & kk) == 0);
                    bool sw = desc ? (a < b) : (a > b);
                    if (sw) { sorted[t] = b; sorted[ixj] = a; }
                }
            }
            __syncthreads();
        }
    }
    float thresh = sorted[HBv - 1];
    if (tid == 0) {
        int cnt = 0;
        for (int j = 0; j < Sq && cnt < HBv; j++)
            if (g_colsum[h * Sq + j] > thresh) g_heavy_idx[h * HBv + cnt++] = j;
        for (int j = 0; j < Sq && cnt < HBv; j++)
            if (g_colsum[h * Sq + j] == thresh) g_heavy_idx[h * HBv + cnt++] = j;
    }
}

// ---------------------------------------------------------------------------
// Sparse attention: block = (16-query tile, head). Kept superset (<=424 cols)
// staged as masked probs in smem; V rows loaded once per tile.
// ---------------------------------------------------------------------------
__global__ __launch_bounds__(256) void attnout2_kernel(const float* __restrict__ v, int ldv)
{
    __shared__ int jl[432];
    __shared__ float ps[432][20];
    __shared__ unsigned char wflag[224];
    __shared__ float psum[16];
    __shared__ float part[16][17];
    __shared__ int n_s;

    int h = blockIdx.y;
    int i0 = blockIdx.x * 16;
    int kv = h >> 2;
    int tid = threadIdx.x;

    int lo0 = i0 - RBv; if (lo0 < 0) lo0 = 0;
    int wlen = i0 + 15 - lo0 + 1;
    for (int t = tid; t < 224; t += 256) wflag[t] = 0;
    for (int t = tid; t < wlen; t += 256) jl[t] = lo0 + t;
    __syncthreads();
    if (tid == 0) {
        int cnt = wlen;
        for (int t = 0; t < HBv; t++) {
            int j = g_heavy_idx[h * HBv + t];
            if (j < lo0) jl[cnt++] = j;
            else if (j <= i0 + 15) wflag[j - lo0] = 1;
        }
        n_s = cnt;
    }
    __syncthreads();
    int n = n_s;

#pragma unroll 1
    for (int q = 0; q < 16; q++) {
        int iq = i0 + q;
        const float* row = &g_scores[((size_t)h * Sq + iq) * Sq];
        for (int t = tid; t < n; t += 256) {
            int j = jl[t];
            float val = 0.f;
            if (j <= iq) {
                bool kept = (t < wlen) ? (j >= iq - RBv || wflag[t]) : true;
                if (kept) val = row[j];
            }
            ps[t][q] = val;
        }
    }
    __syncthreads();

    {
        int q = tid >> 4, c = tid & 15;
        float s = 0.f;
        for (int t = c; t < n; t += 16) s += ps[t][q];
        part[q][c] = s;
    }
    __syncthreads();
    if (tid < 16) {
        float s = 0.f;
#pragma unroll
        for (int c = 0; c < 16; c++) s += part[tid][c];
        psum[tid] = s;
    }
    __syncthreads();

    int d = tid & 127, hlf = tid >> 7;
    float acc[16];
#pragma unroll
    for (int q = 0; q < 16; q++) acc[q] = 0.f;
    for (int t = hlf; t < n; t += 2) {
        float vv = v[(size_t)jl[t] * ldv + kv * Dv + d];
        const float4* pr = reinterpret_cast<const float4*>(&ps[t][0]);
#pragma unroll
        for (int qq = 0; qq < 4; qq++) {
            float4 p4 = pr[qq];
            acc[qq * 4 + 0] += p4.x * vv;
            acc[qq * 4 + 1] += p4.y * vv;
            acc[qq * 4 + 2] += p4.z * vv;
            acc[qq * 4 + 3] += p4.w * vv;
        }
    }
    __syncthreads();
    float* comb = &ps[0][0];
    if (hlf == 1) {
#pragma unroll
        for (int q = 0; q < 16; q++) comb[d * 16 + q] = acc[q];
    }
    __syncthreads();
    if (hlf == 0) {
#pragma unroll
        for (int q = 0; q < 16; q++) {
            float o = (acc[q] + comb[d * 16 + q]) / psum[q];
            g_attn16[(size_t)(i0 + q) * HIDv + h * Dv + d] = __float2half_rn(o);
        }
    }
}

// ---------------------------------------------------------------------------
extern "C" void kernel_launch(void* const* d_in, const int* in_sizes, int n_in,
                              void* d_out, int out_size)
{
    const float* hs = (const float*)d_in[0];
    const float* Wq = (const float*)d_in[1];
    const float* Wk = (const float*)d_in[2];
    const float* Wv = (const float*)d_in[3];
    const float* Wo = (const float*)d_in[4];
    float* out = (float*)d_out;

    void* p;
    cudaGetSymbolAddress(&p, g_hs16);   __half* hs16 = (__half*)p;
    cudaGetSymbolAddress(&p, g_wt16);   __half* wt16 = (__half*)p;
    cudaGetSymbolAddress(&p, g_qkv);    float*  qkv  = (float*)p;
    cudaGetSymbolAddress(&p, g_q16);    __half* q16  = (__half*)p;
    cudaGetSymbolAddress(&p, g_k16);    __half* k16  = (__half*)p;
    cudaGetSymbolAddress(&p, g_attn16); __half* at16 = (__half*)p;

    cudaFuncSetAttribute(gemm_h_kernel,
                         cudaFuncAttributeMaxDynamicSharedMemorySize, SMEM_H);
    cudaFuncSetAttribute(scores_h_kernel,
                         cudaFuncAttributeMaxDynamicSharedMemorySize, SMEM_H);

    dim3 tb(32, 8);

    // Inputs to fp16 + trig table
    trig_kernel<<<512, 256>>>();
    f2h_kernel<<<(2048 * 2048 / 4 + 255) / 256, 256>>>(hs, hs16, 2048 * 2048 / 4);
    transpose_h_kernel<<<dim3(HIDv / 32, HIDv / 32), tb>>>(Wq, wt16, HIDv, HIDv);
    transpose_h_kernel<<<dim3((NKVv * Dv) / 32, HIDv / 32), tb>>>(
        Wk, wt16 + (size_t)2048 * HIDv, HIDv, NKVv * Dv);
    transpose_h_kernel<<<dim3((NKVv * Dv) / 32, HIDv / 32), tb>>>(
        Wv, wt16 + (size_t)2560 * HIDv, HIDv, NKVv * Dv);

    // Fused QKV projection
    gemm_h_kernel<<<dim3(QKV / 128, Sq / 128), 256, SMEM_H>>>(
        hs16, HIDv, wt16, HIDv, qkv, QKV, HIDv);

    // RoPE -> fp16 q/k
    rope_h_kernel<<<(Sq * NHv * 64 + 255) / 256, 256>>>(qkv, 0, q16, NHv, 2048);
    rope_h_kernel<<<(Sq * NKVv * 64 + 255) / 256, 256>>>(qkv, 2048, k16, NKVv, 512);

    // Causal scores + fused exp + rowsum partials
    scores_h_kernel<<<dim3(Sq / 128, Sq / 128, NHv), 256, SMEM_H>>>(q16, k16);
    rowsumred_kernel<<<dim3(Sq / 256, NHv), 256>>>();

    // H2O oracle
    colsum_kernel<<<dim3(Sq / 16, NHv), 256>>>();
    colreduce_kernel<<<dim3(Sq / 256, NHv), 256>>>();
    topk_kernel<<<NHv, 1024>>>();

    // Sparse attention
    attnout2_kernel<<<dim3(Sq / 16, NHv), 256>>>(qkv + 2560, QKV);

    // Output projection
    transpose_h_kernel<<<dim3(HIDv / 32, HIDv / 32), tb>>>(Wo, wt16, HIDv, HIDv);
    gemm_h_kernel<<<dim3(HIDv / 128, Sq / 128), 256, SMEM_H>>>(
        at16, HIDv, wt16, HIDv, out, HIDv, HIDv);
}